// round 6
// baseline (speedup 1.0000x reference)
#include <cuda_runtime.h>
#include <cstdint>

// ---------------------------------------------------------------------------
// Scratch buffers (static __device__ globals — no allocation allowed).
// ---------------------------------------------------------------------------
__device__ float g_bufA[33554432];
__device__ float g_bufC[33554432];
__device__ float g_wt[262144];          // preprocessed (tf32 + permuted) weights

// ---------------------------------------------------------------------------
// Helpers
// ---------------------------------------------------------------------------
__device__ __forceinline__ float tf32r(float x)
{
    uint32_t u;
    asm("cvt.rna.tf32.f32 %0, %1;" : "=r"(u) : "f"(x));
    return __uint_as_float(u);
}

__device__ __forceinline__ void mma_tf32(float* c,
                                         uint32_t a0, uint32_t a1,
                                         uint32_t a2, uint32_t a3,
                                         uint32_t b0, uint32_t b1)
{
    asm volatile(
        "mma.sync.aligned.m16n8k8.row.col.f32.tf32.tf32.f32 "
        "{%0,%1,%2,%3}, {%4,%5,%6,%7}, {%8,%9}, {%0,%1,%2,%3};\n"
        : "+f"(c[0]), "+f"(c[1]), "+f"(c[2]), "+f"(c[3])
        : "r"(a0), "r"(a1), "r"(a2), "r"(a3), "r"(b0), "r"(b1));
}

__device__ __forceinline__ uint32_t smem_u32(const void* p)
{
    return (uint32_t)__cvta_generic_to_shared(p);
}

// 16B cp.async; src-size 0 -> 16 zero bytes written (used for halo padding).
__device__ __forceinline__ void cp16z(uint32_t dst, const float* src, bool ok)
{
    int sz = ok ? 16 : 0;
    asm volatile("cp.async.ca.shared.global [%0], [%1], 16, %2;"
                 :: "r"(dst), "l"(src), "r"(sz));
}

// ---------------------------------------------------------------------------
// Implicit-GEMM 3x3 conv (pad=1), tf32 mma.sync.m16n8k8, cp.async
// double-buffered K-chunk pipeline. Inputs/weights pre-rounded to tf32.
// Weights pre-permuted so each A fragment is two LDS.64.
//
// DEFORM=1: fused ConvOffset2D epilogue. The torch raw-reshape maps deform
// output flat index G (= c*HW + h*W + w) to offset pair at flat offconv
// indices (2G, 2G+1) — exactly the even/odd column pair each thread holds.
// So the epilogue directly bilinear-samples `in` and scatters the deform
// result; the offset tensor is never materialized.
// ---------------------------------------------------------------------------
template<int STRIDE, int CIN, int BR, int DEFORM>
__global__ __launch_bounds__(256, 2)
void conv3x3_tc(const float* __restrict__ in, const float* __restrict__ w,
                const float* __restrict__ bias, float* __restrict__ out,
                int Cout, int Hin, int Win, int wsh, int hsh)
{
    constexpr int TH = 4, TW = 32;
    constexpr int TIH  = TH * STRIDE + 2;               // 6 / 10
    constexpr int TIWP = (TW * STRIDE + 5 + 3) & ~3;    // 40 / 72
    constexpr int RU   = TIWP / 4;                      // 16B units per row
    constexpr int CHE  = TIH * TIWP;
    constexpr int TILE_N = 8 * CHE;
    constexpr int NCH  = CIN / 8;
    constexpr int WSTR = 76;
    constexpr int WN   = 32 * WSTR;
    constexpr int TU   = 8 * TIH * RU;
    constexpr int TITER = (TU + 255) / 256;
    constexpr int WU   = 32 * 18;                       // 576 16B units
    constexpr int WITER = (WU + 255) / 256;

    extern __shared__ __align__(16) float smem[];       // [tile0|tile1|w0|w1]
    __shared__ int s_koff[72];

    const int Hout = Hin / STRIDE, Wout = Win / STRIDE;
    const int tid = threadIdx.x;
    const int groups = Cout >> 5;
    const int g  = blockIdx.z % groups;
    const int b  = blockIdx.z / groups;
    const int bx = blockIdx.x, by = blockIdx.y;

    if (tid < 72) {
        int ci8 = tid / 9, r = tid % 9;
        s_koff[tid] = ci8 * CHE + (r / 3) * TIWP + (r % 3);
    }

    const int y0 = by * TH * STRIDE - 1;
    const int x0 = bx * TW * STRIDE - 4;    // 16B-aligned halo (logical -1 = col 3)
    const size_t HW = (size_t)Hin * Win;
    const float* ibase = in + (size_t)b * CIN * HW;

    // --- hoisted staging descriptors (advance affinely per chunk) ---
    const float* tsrc[TITER];
    uint32_t     tdoff[TITER];
    bool         tok[TITER];
    #pragma unroll
    for (int it = 0; it < TITER; it++) {
        int u = tid + it * 256;
        int uc = (u < TU) ? u : 0;
        int ci8 = uc / (TIH * RU);
        int rem = uc - ci8 * (TIH * RU);
        int r = rem / RU, uu = rem - r * RU;
        int gy = y0 + r, gx = x0 + 4 * uu;
        tok[it] = (gy >= 0) && (gy < Hin) && (gx >= 0) && (gx < Win);
        tsrc[it] = ibase + (size_t)ci8 * HW + (size_t)gy * Win + gx;
        tdoff[it] = 4u * (uint32_t)(ci8 * CHE + r * TIWP + 4 * uu);
    }
    const float* wsrc[WITER];
    uint32_t     wdoff[WITER];
    {
        const float* wg0 = w + (size_t)g * NCH * 2304;  // [g][ch][co][72]
        #pragma unroll
        for (int it = 0; it < WITER; it++) {
            int u = tid + it * 256;
            int uc = (u < WU) ? u : 0;
            int co = uc / 18, k4 = uc - co * 18;
            wsrc[it] = wg0 + co * 72 + 4 * k4;
            wdoff[it] = 4u * (uint32_t)(co * WSTR + 4 * k4);
        }
    }

    const uint32_t tile_s = smem_u32(smem);
    const uint32_t wbuf_s = smem_u32(smem + 2 * TILE_N);

    auto load_chunk = [&](int bi) {
        uint32_t td = tile_s + (bi ? 4u * TILE_N : 0u);
        #pragma unroll
        for (int it = 0; it < TITER; it++)
            if (tid + it * 256 < TU) {
                cp16z(td + tdoff[it], tsrc[it], tok[it]);
                tsrc[it] += 8 * HW;
            }
        uint32_t wd = wbuf_s + (bi ? 4u * WN : 0u);
        #pragma unroll
        for (int it = 0; it < WITER; it++)
            if (tid + it * 256 < WU) {
                cp16z(wd + wdoff[it], wsrc[it], true);
                wsrc[it] += 2304;
            }
        asm volatile("cp.async.commit_group;");
    };

    const int lane = tid & 31, wid = tid >> 5;
    const int tig = lane & 3, gid = lane >> 2;
    const int mh = wid & 1;
    const int nq = wid >> 1;

    float acc[4][4];
    {
        float bv0 = 0.0f, bv1 = 0.0f;
        if (BR) {
            bv0 = bias[g * 32 + mh * 16 + gid];
            bv1 = bias[g * 32 + mh * 16 + gid + 8];
        }
        #pragma unroll
        for (int t = 0; t < 4; t++) {
            acc[t][0] = bv0; acc[t][1] = bv0;
            acc[t][2] = bv1; acc[t][3] = bv1;
        }
    }

    load_chunk(0);

    #pragma unroll
    for (int ch = 0; ch < NCH; ch++) {
        const int cur = ch & 1;
        if (ch + 1 < NCH) {
            load_chunk(cur ^ 1);
            asm volatile("cp.async.wait_group 1;");
        } else {
            asm volatile("cp.async.wait_group 0;");
        }
        __syncthreads();

        const float* st = smem + cur * TILE_N;
        const float* sw = smem + 2 * TILE_N + cur * WN;
        const int bb = nq * STRIDE * TIWP + gid * STRIDE + 3;
        const float* ap0 = sw + (mh * 16 + gid) * WSTR + 2 * tig;

        #pragma unroll
        for (int ks = 0; ks < 9; ks++) {
            const int ko1 = s_koff[ks * 8 + tig];
            const int ko2 = s_koff[ks * 8 + tig + 4];
            // permuted layout: [k=tig | k=tig+4] adjacent -> LDS.64
            float2 wlo = *reinterpret_cast<const float2*>(ap0 + ks * 8);
            float2 whi = *reinterpret_cast<const float2*>(ap0 + ks * 8 + 8 * WSTR);
            uint32_t a0 = __float_as_uint(wlo.x);
            uint32_t a2 = __float_as_uint(wlo.y);
            uint32_t a1 = __float_as_uint(whi.x);
            uint32_t a3 = __float_as_uint(whi.y);
            #pragma unroll
            for (int t = 0; t < 4; t++) {
                uint32_t b0 = __float_as_uint(st[ko1 + bb + t * 8 * STRIDE]);
                uint32_t b1 = __float_as_uint(st[ko2 + bb + t * 8 * STRIDE]);
                mma_tf32(acc[t], a0, a1, a2, a3, b0, b1);
            }
        }
        __syncthreads();
    }

    const int co0 = g * 32 + mh * 16 + gid;
    const int hrow = by * TH + nq;

    if (DEFORM) {
        // Fused ConvOffset2D: each even/odd column pair = one deform output.
        const int Wm1 = Win - 1, Hm1 = Hin - 1;
        float* ob = out + (size_t)b * CIN * HW;
        #pragma unroll
        for (int t = 0; t < 4; t++) {
            #pragma unroll
            for (int hf = 0; hf < 2; hf++) {
                float o0 = acc[t][hf * 2 + 0];
                float o1 = acc[t][hf * 2 + 1];
                const int co = co0 + hf * 8;
                const int wg = bx * 32 + t * 8 + 2 * tig;
                const unsigned F = (unsigned)co * (unsigned)HW
                                 + ((unsigned)hrow << wsh) + (unsigned)wg;
                const unsigned G = F >> 1;
                const int ww = G & Wm1;
                const int hh = (G >> wsh) & Hm1;
                const int cc = G >> (wsh + hsh);
                float r  = fminf(fmaxf(o0 + (float)hh, 0.0f), (float)Hm1);
                float cl = fminf(fmaxf(o1 + (float)ww, 0.0f), (float)Wm1);
                float r0f = floorf(r), c0f = floorf(cl);
                int r0 = (int)r0f, r1 = (int)ceilf(r);
                int c0i = (int)c0f, c1 = (int)ceilf(cl);
                const float* xp = ibase + (size_t)cc * HW;
                float vlt = xp[(r0 << wsh) + c0i];
                float vrb = xp[(r1 << wsh) + c1];
                float vlb = xp[(r0 << wsh) + c1];
                float vrt = xp[(r1 << wsh) + c0i];
                float fr = r - r0f, fc = cl - c0f;
                float vt = vlt + (vrt - vlt) * fr;
                float vb = vlb + (vrb - vlb) * fr;
                ob[G] = tf32r(vt + (vb - vt) * fc);
            }
        }
    } else {
        #pragma unroll
        for (int t = 0; t < 4; t++) {
            float2 lo, hi;
            if (BR) {
                lo = make_float2(tf32r(fmaxf(acc[t][0], 0.0f)), tf32r(fmaxf(acc[t][1], 0.0f)));
                hi = make_float2(tf32r(fmaxf(acc[t][2], 0.0f)), tf32r(fmaxf(acc[t][3], 0.0f)));
            } else {
                lo = make_float2(tf32r(acc[t][0]), tf32r(acc[t][1]));
                hi = make_float2(tf32r(acc[t][2]), tf32r(acc[t][3]));
            }
            const int wg = bx * 32 + t * 8 + 2 * tig;
            *reinterpret_cast<float2*>(
                out + (((size_t)b * Cout + co0) * Hout + hrow) * Wout + wg) = lo;
            *reinterpret_cast<float2*>(
                out + (((size_t)b * Cout + co0 + 8) * Hout + hrow) * Wout + wg) = hi;
        }
    }
}

// ---------------------------------------------------------------------------
// Weight prepass: tf32-round + permute into [g][ch][co32][ks][j'] where
// j = (j'&1)*4 + (j'>>1)  (pairs k and k+4 adjacent for LDS.64 A fragments).
// ---------------------------------------------------------------------------
__global__ void prep_w(const float* __restrict__ w, float* __restrict__ dst,
                       int Cout, int CIN)
{
    int i = blockIdx.x * 256 + threadIdx.x;
    int total = Cout * CIN * 9;
    if (i >= total) return;
    int kk2 = i % 72;
    int rest = i / 72;
    int co = rest & 31; rest >>= 5;
    int NCH = CIN >> 3;
    int ch = rest % NCH;
    int gi = rest / NCH;
    int ks = kk2 >> 3, jp = kk2 & 7;
    int j = (jp & 1) * 4 + (jp >> 1);
    int kk = ks * 8 + j;
    int ci8 = kk / 9, r = kk % 9;
    dst[i] = tf32r(w[(((size_t)(gi * 32 + co)) * CIN + ch * 8 + ci8) * 9 + r]);
}

// ---------------------------------------------------------------------------
// tf32 rounding prepass for x (vectorized).
// ---------------------------------------------------------------------------
__global__ void cvt4_kernel(const float4* __restrict__ src,
                            float4* __restrict__ dst, int n4)
{
    int i = blockIdx.x * 256 + threadIdx.x;
    if (i >= n4) return;
    float4 v = src[i];
    v.x = tf32r(v.x); v.y = tf32r(v.y); v.z = tf32r(v.z); v.w = tf32r(v.w);
    dst[i] = v;
}

// ---------------------------------------------------------------------------
// Global average pool over H*W. One block per (b, c).
// ---------------------------------------------------------------------------
__global__ void avgpool_kernel(const float* __restrict__ in,
                               float* __restrict__ out, int HW)
{
    const float* p = in + (size_t)blockIdx.x * HW;
    float s = 0.0f;
    for (int i = threadIdx.x; i < HW; i += blockDim.x) s += p[i];
    __shared__ float sm[256];
    sm[threadIdx.x] = s;
    __syncthreads();
    for (int st = 128; st > 0; st >>= 1) {
        if (threadIdx.x < st) sm[threadIdx.x] += sm[threadIdx.x + st];
        __syncthreads();
    }
    if (threadIdx.x == 0) out[blockIdx.x] = sm[0] / (float)HW;
}

// ---------------------------------------------------------------------------
// Launch pipeline (graph-capturable: kernel launches + attribute sets only).
// ---------------------------------------------------------------------------
static inline int conv_smem_bytes(int stride)
{
    int tih  = 4 * stride + 2;
    int tiwp = (32 * stride + 5 + 3) & ~3;
    int tile_n = 8 * tih * tiwp;
    return (2 * tile_n + 2 * (32 * 76)) * 4;   // 34816 (s1) / 65536 (s2)
}

extern "C" void kernel_launch(void* const* d_in, const int* in_sizes, int n_in,
                              void* d_out, int out_size)
{
    const float* x   = (const float*)d_in[0];
    const float* w1  = (const float*)d_in[1];
    const float* b1  = (const float*)d_in[2];
    const float* ow1 = (const float*)d_in[3];
    const float* w2  = (const float*)d_in[4];
    const float* b2  = (const float*)d_in[5];
    const float* ow2 = (const float*)d_in[6];
    const float* w3  = (const float*)d_in[7];
    const float* b3  = (const float*)d_in[8];
    const float* ow3 = (const float*)d_in[9];
    const float* w4  = (const float*)d_in[10];
    const float* b4  = (const float*)d_in[11];
    float* outp = (float*)d_out;

    float *A, *C, *WT;
    cudaGetSymbolAddress((void**)&A, g_bufA);
    cudaGetSymbolAddress((void**)&C, g_bufC);
    cudaGetSymbolAddress((void**)&WT, g_wt);

    const int S1 = conv_smem_bytes(1), S2 = conv_smem_bytes(2);
    cudaFuncSetAttribute(conv3x3_tc<1, 32, 1, 0>, cudaFuncAttributeMaxDynamicSharedMemorySize, S1);
    cudaFuncSetAttribute(conv3x3_tc<1, 32, 0, 1>, cudaFuncAttributeMaxDynamicSharedMemorySize, S1);
    cudaFuncSetAttribute(conv3x3_tc<1, 64, 0, 1>, cudaFuncAttributeMaxDynamicSharedMemorySize, S1);
    cudaFuncSetAttribute(conv3x3_tc<2, 32, 1, 0>, cudaFuncAttributeMaxDynamicSharedMemorySize, S2);
    cudaFuncSetAttribute(conv3x3_tc<2, 64, 1, 0>, cudaFuncAttributeMaxDynamicSharedMemorySize, S2);

    // Preprocessed weights in g_wt
    float* w1t  = WT;             // 9216
    float* ow1t = WT + 9216;      // 18432
    float* w2t  = WT + 27648;     // 18432
    float* ow2t = WT + 46080;     // 73728
    float* w3t  = WT + 119808;    // 18432
    float* ow3t = WT + 138240;    // 18432
    float* w4t  = WT + 156672;    // 9216

    auto prep = [](const float* s, float* d, int Cout, int CIN) {
        int n = Cout * CIN * 9;
        prep_w<<<(n + 255) / 256, 256>>>(s, d, Cout, CIN);
    };
    prep(w1, w1t, 32, 32);    prep(ow1, ow1t, 64, 32);
    prep(w2, w2t, 64, 32);    prep(ow2, ow2t, 128, 64);
    prep(w3, w3t, 32, 64);    prep(ow3, ow3t, 64, 32);
    prep(w4, w4t, 32, 32);
    {
        int n4 = 16 * 32 * 256 * 256 / 4;
        cvt4_kernel<<<(n4 + 255) / 256, 256>>>((const float4*)x, (float4*)C, n4);
    }

    // 1) conv1: C(x~) -> A (16,32,256,256), bias+relu
    conv3x3_tc<1, 32, 1, 0><<<dim3(8, 64, 16), 256, S1>>>(C, w1t, b1, A, 32, 256, 256, 8, 8);

    // 2+3) offconv1 + fused deform1: A -> C (16,32,256,256)
    conv3x3_tc<1, 32, 0, 1><<<dim3(8, 64, 32), 256, S1>>>(A, ow1t, nullptr, C, 64, 256, 256, 8, 8);

    // 4) conv2 stride2: C -> A (16,64,128,128), bias+relu
    conv3x3_tc<2, 32, 1, 0><<<dim3(4, 32, 32), 256, S2>>>(C, w2t, b2, A, 64, 256, 256, 7, 7);

    // 5+6) offconv2 + fused deform2: A -> C (16,64,128,128)
    conv3x3_tc<1, 64, 0, 1><<<dim3(4, 32, 64), 256, S1>>>(A, ow2t, nullptr, C, 128, 128, 128, 7, 7);

    // 7) conv3 stride2: C -> A (16,32,64,64), bias+relu
    conv3x3_tc<2, 64, 1, 0><<<dim3(2, 16, 16), 256, S2>>>(C, w3t, b3, A, 32, 128, 128, 6, 6);

    // 8+9) offconv3 + fused deform3: A -> C (16,32,64,64)
    conv3x3_tc<1, 32, 0, 1><<<dim3(2, 16, 32), 256, S1>>>(A, ow3t, nullptr, C, 64, 64, 64, 6, 6);

    // 10) conv4 stride2: C -> A (16,32,32,32), bias+relu
    conv3x3_tc<2, 32, 1, 0><<<dim3(1, 8, 16), 256, S2>>>(C, w4t, b4, A, 32, 64, 64, 5, 5);

    // 11) global avg pool -> (16,32,1,1)
    avgpool_kernel<<<512, 256>>>(A, outp, 32 * 32);
}

// round 7
// speedup vs baseline: 1.1966x; 1.1966x over previous
#include <cuda_runtime.h>
#include <cstdint>

// ---------------------------------------------------------------------------
// Scratch buffers (static __device__ globals — no allocation allowed).
// ---------------------------------------------------------------------------
__device__ float g_bufA[33554432];
__device__ float g_bufB[67108864];
__device__ float g_bufC[33554432];
__device__ float g_wt[262144];          // preprocessed (tf32 + permuted) weights

// ---------------------------------------------------------------------------
// Helpers
// ---------------------------------------------------------------------------
__device__ __forceinline__ float tf32r(float x)
{
    uint32_t u;
    asm("cvt.rna.tf32.f32 %0, %1;" : "=r"(u) : "f"(x));
    return __uint_as_float(u);
}

__device__ __forceinline__ void mma_tf32(float* c,
                                         uint32_t a0, uint32_t a1,
                                         uint32_t a2, uint32_t a3,
                                         uint32_t b0, uint32_t b1)
{
    asm volatile(
        "mma.sync.aligned.m16n8k8.row.col.f32.tf32.tf32.f32 "
        "{%0,%1,%2,%3}, {%4,%5,%6,%7}, {%8,%9}, {%0,%1,%2,%3};\n"
        : "+f"(c[0]), "+f"(c[1]), "+f"(c[2]), "+f"(c[3])
        : "r"(a0), "r"(a1), "r"(a2), "r"(a3), "r"(b0), "r"(b1));
}

__device__ __forceinline__ uint32_t smem_u32(const void* p)
{
    return (uint32_t)__cvta_generic_to_shared(p);
}

// 16B cp.async; src-size 0 -> 16 zero bytes written (halo padding).
__device__ __forceinline__ void cp16z(uint32_t dst, const float* src, bool ok)
{
    int sz = ok ? 16 : 0;
    asm volatile("cp.async.ca.shared.global [%0], [%1], 16, %2;"
                 :: "r"(dst), "l"(src), "r"(sz));
}

// ---------------------------------------------------------------------------
// Implicit-GEMM 3x3 conv (pad=1), tf32 mma.sync.m16n8k8, cp.async
// double-buffered K-chunk pipeline. Inputs/weights pre-rounded to tf32;
// weights pre-permuted so each A fragment is two LDS.64.
//
// Output tile: 32 couts x (TH h x 32 w). Block = 256 thr (8 warps).
//  TH=4 (stride-2): warp = (co half mh, row nq=wid>>2*?); 1 M-tile/warp.
//  TH=8 (stride-1): warp = one row (nq=wid); 2 M-tiles/warp, B frags
//    loaded once and reused across both M-tiles (halves LDS per MMA).
// ---------------------------------------------------------------------------
template<int STRIDE, int CIN, int BR, int TH>
__global__ __launch_bounds__(256, 2)
void conv3x3_tc(const float* __restrict__ in, const float* __restrict__ w,
                const float* __restrict__ bias, float* __restrict__ out,
                int Cout, int Hin, int Win)
{
    constexpr int TW = 32;
    constexpr int M    = (TH == 8) ? 2 : 1;             // M-tiles per warp
    constexpr int TIH  = TH * STRIDE + 2;               // 10 / 10
    constexpr int TIWP = (TW * STRIDE + 5 + 3) & ~3;    // 40 / 72
    constexpr int RU   = TIWP / 4;
    constexpr int CHE  = TIH * TIWP;
    constexpr int TILE_N = 8 * CHE;
    constexpr int NCH  = CIN / 8;
    constexpr int WSTR = 76;
    constexpr int WN   = 32 * WSTR;
    constexpr int TU   = 8 * TIH * RU;
    constexpr int WU   = 32 * 18;

    extern __shared__ __align__(16) float smem[];       // [tile0|tile1|w0|w1]
    __shared__ int s_koff[72];

    const int Hout = Hin / STRIDE, Wout = Win / STRIDE;
    const int tid = threadIdx.x;
    const int groups = Cout >> 5;
    const int g  = blockIdx.z % groups;
    const int b  = blockIdx.z / groups;
    const int bx = blockIdx.x, by = blockIdx.y;

    if (tid < 72) {
        int ci8 = tid / 9, r = tid % 9;
        s_koff[tid] = ci8 * CHE + (r / 3) * TIWP + (r % 3);
    }

    const int y0 = by * TH * STRIDE - 1;
    const int x0 = bx * TW * STRIDE - 4;    // 16B-aligned halo (logical -1 = col 3)
    const size_t HW = (size_t)Hin * Win;
    const float* ibase = in + (size_t)b * CIN * HW;
    const float* wbase = w + (size_t)g * NCH * 2304;    // [g][ch][co32][72]

    const uint32_t tile_s = smem_u32(smem);
    const uint32_t wbuf_s = smem_u32(smem + 2 * TILE_N);

    auto load_chunk = [&](int ch, int bi) {
        const float* isrc = ibase + (size_t)(ch * 8) * HW;
        uint32_t td = tile_s + (bi ? 4u * TILE_N : 0u);
        #pragma unroll 4
        for (int u = tid; u < TU; u += 256) {
            int ci8 = u / (TIH * RU);
            int rem = u - ci8 * (TIH * RU);
            int r = rem / RU, uu = rem - r * RU;
            int gy = y0 + r, gx = x0 + 4 * uu;
            bool ok = (gy >= 0) && (gy < Hin) && (gx >= 0) && (gx < Win);
            cp16z(td + 4u * (uint32_t)(ci8 * CHE + r * TIWP + 4 * uu),
                  isrc + (size_t)ci8 * HW + (size_t)gy * Win + gx, ok);
        }
        const float* wsrc = wbase + ch * 2304;
        uint32_t wd = wbuf_s + (bi ? 4u * WN : 0u);
        #pragma unroll 3
        for (int u = tid; u < WU; u += 256) {
            int co = u / 18, k4 = u - co * 18;
            cp16z(wd + 4u * (uint32_t)(co * WSTR + 4 * k4),
                  wsrc + co * 72 + 4 * k4, true);
        }
        asm volatile("cp.async.commit_group;");
    };

    const int lane = tid & 31, wid = tid >> 5;
    const int tig = lane & 3, gid = lane >> 2;
    const int mh = (TH == 8) ? 0 : (wid & 1);           // co half (TH=4 only)
    const int nq = (TH == 8) ? wid : (wid >> 1);        // output row in tile

    float acc[M][4][4];
    #pragma unroll
    for (int m = 0; m < M; m++) {
        const int cb = (TH == 8) ? m * 16 : mh * 16;
        float bv0 = 0.0f, bv1 = 0.0f;
        if (BR) {
            bv0 = bias[g * 32 + cb + gid];
            bv1 = bias[g * 32 + cb + gid + 8];
        }
        #pragma unroll
        for (int t = 0; t < 4; t++) {
            acc[m][t][0] = bv0; acc[m][t][1] = bv0;
            acc[m][t][2] = bv1; acc[m][t][3] = bv1;
        }
    }

    load_chunk(0, 0);

    #pragma unroll
    for (int ch = 0; ch < NCH; ch++) {
        const int cur = ch & 1;
        if (ch + 1 < NCH) {
            load_chunk(ch + 1, cur ^ 1);
            asm volatile("cp.async.wait_group 1;");
        } else {
            asm volatile("cp.async.wait_group 0;");
        }
        __syncthreads();

        const float* st = smem + cur * TILE_N;
        const float* sw = smem + 2 * TILE_N + cur * WN;
        const int bb = nq * STRIDE * TIWP + gid * STRIDE + 3;

        #pragma unroll
        for (int ks = 0; ks < 9; ks++) {
            const int ko1 = s_koff[ks * 8 + tig];
            const int ko2 = s_koff[ks * 8 + tig + 4];
            // A fragments (permuted layout: k=tig | k=tig+4 adjacent -> LDS.64)
            uint32_t a0[M], a1[M], a2[M], a3[M];
            #pragma unroll
            for (int m = 0; m < M; m++) {
                const int cb = (TH == 8) ? m * 16 : mh * 16;
                const float* ap = sw + (cb + gid) * WSTR + 2 * tig + ks * 8;
                float2 wlo = *reinterpret_cast<const float2*>(ap);
                float2 whi = *reinterpret_cast<const float2*>(ap + 8 * WSTR);
                a0[m] = __float_as_uint(wlo.x);
                a2[m] = __float_as_uint(wlo.y);
                a1[m] = __float_as_uint(whi.x);
                a3[m] = __float_as_uint(whi.y);
            }
            #pragma unroll
            for (int t = 0; t < 4; t++) {
                uint32_t b0 = __float_as_uint(st[ko1 + bb + t * 8 * STRIDE]);
                uint32_t b1 = __float_as_uint(st[ko2 + bb + t * 8 * STRIDE]);
                #pragma unroll
                for (int m = 0; m < M; m++)
                    mma_tf32(acc[m][t], a0[m], a1[m], a2[m], a3[m], b0, b1);
            }
        }
        __syncthreads();
    }

    // Epilogue (tf32-rounded so consumers can cp.async raw bits).
    const int hrow = by * TH + nq;
    #pragma unroll
    for (int m = 0; m < M; m++) {
        const int cb = (TH == 8) ? m * 16 : mh * 16;
        const int co0 = g * 32 + cb + gid;
        #pragma unroll
        for (int t = 0; t < 4; t++) {
            float2 lo, hi;
            if (BR) {
                lo = make_float2(tf32r(fmaxf(acc[m][t][0], 0.0f)),
                                 tf32r(fmaxf(acc[m][t][1], 0.0f)));
                hi = make_float2(tf32r(fmaxf(acc[m][t][2], 0.0f)),
                                 tf32r(fmaxf(acc[m][t][3], 0.0f)));
            } else {
                lo = make_float2(tf32r(acc[m][t][0]), tf32r(acc[m][t][1]));
                hi = make_float2(tf32r(acc[m][t][2]), tf32r(acc[m][t][3]));
            }
            const int wg = bx * 32 + t * 8 + 2 * tig;
            *reinterpret_cast<float2*>(
                out + (((size_t)b * Cout + co0) * Hout + hrow) * Wout + wg) = lo;
            *reinterpret_cast<float2*>(
                out + (((size_t)b * Cout + co0 + 8) * Hout + hrow) * Wout + wg) = hi;
        }
    }
}

// ---------------------------------------------------------------------------
// ConvOffset2D bilinear sampling (faithful torch-style raw reshape).
// Output rounded to tf32 (consumed raw by next conv).
// ---------------------------------------------------------------------------
__global__ void deform_kernel(const float* __restrict__ x,
                              const float* __restrict__ off,
                              float* __restrict__ out,
                              int wsh, int hsh, int csh, int total)
{
    int idx = blockIdx.x * blockDim.x + threadIdx.x;
    if (idx >= total) return;
    const int W = 1 << wsh, H = 1 << hsh, C = 1 << csh;
    int w = idx & (W - 1);
    int h = (idx >> wsh) & (H - 1);
    int c = (idx >> (wsh + hsh)) & (C - 1);
    int b = idx >> (wsh + hsh + csh);

    size_t HW = (size_t)H * W;
    size_t obase = ((size_t)((b << csh) + c) * 2) * HW + 2 * (size_t)((h << wsh) + w);
    float o0 = off[obase];
    float o1 = off[obase + 1];

    float r  = fminf(fmaxf(o0 + (float)h, 0.0f), (float)(H - 1));
    float cc = fminf(fmaxf(o1 + (float)w, 0.0f), (float)(W - 1));
    float r0f = floorf(r), c0f = floorf(cc);
    int r0 = (int)r0f;
    int r1 = (int)ceilf(r);
    int c0 = (int)c0f;
    int c1 = (int)ceilf(cc);

    const float* xb = x + (((size_t)(b << csh) + c)) * HW;
    float v_lt = xb[(r0 << wsh) + c0];
    float v_rb = xb[(r1 << wsh) + c1];
    float v_lb = xb[(r0 << wsh) + c1];
    float v_rt = xb[(r1 << wsh) + c0];
    float fr = r - r0f;
    float fc = cc - c0f;
    float vt = v_lt + (v_rt - v_lt) * fr;
    float vb = v_lb + (v_rb - v_lb) * fr;
    out[idx] = tf32r(vt + (vb - vt) * fc);
}

// ---------------------------------------------------------------------------
// Merged weight prepass (ONE launch): tf32-round + permute all 7 weight
// tensors into [g][ch][co32][ks][j'] (j = (j'&1)*4 + (j'>>1)).
// Segment table passed by value as a kernel argument.
// ---------------------------------------------------------------------------
struct PrepDesc {
    const float* src[7];
    int cin[7];         // input channels per tensor
    int off[8];         // prefix sums of element counts (dst offsets)
};

__global__ void prep_all(PrepDesc d, float* __restrict__ dst)
{
    int i = blockIdx.x * 256 + threadIdx.x;
    if (i >= d.off[7]) return;
    int s = 0;
    #pragma unroll
    for (int k = 0; k < 6; k++) s += (i >= d.off[k + 1]) ? 1 : 0;
    int j = i - d.off[s];
    const int CIN = d.cin[s];
    const int NCH = CIN >> 3;

    int kk2 = j % 72;
    int rest = j / 72;
    int co = rest & 31; rest >>= 5;
    int ch = rest % NCH;
    int gi = rest / NCH;
    int ks = kk2 >> 3, jp = kk2 & 7;
    int jj = (jp & 1) * 4 + (jp >> 1);
    int kk = ks * 8 + jj;
    int ci8 = kk / 9, r = kk % 9;
    dst[i] = tf32r(d.src[s][(((size_t)(gi * 32 + co)) * CIN + ch * 8 + ci8) * 9 + r]);
}

// ---------------------------------------------------------------------------
// tf32 rounding prepass for x (vectorized).
// ---------------------------------------------------------------------------
__global__ void cvt4_kernel(const float4* __restrict__ src,
                            float4* __restrict__ dst, int n4)
{
    int i = blockIdx.x * 256 + threadIdx.x;
    if (i >= n4) return;
    float4 v = src[i];
    v.x = tf32r(v.x); v.y = tf32r(v.y); v.z = tf32r(v.z); v.w = tf32r(v.w);
    dst[i] = v;
}

// ---------------------------------------------------------------------------
// Global average pool over H*W. One block per (b, c).
// ---------------------------------------------------------------------------
__global__ void avgpool_kernel(const float* __restrict__ in,
                               float* __restrict__ out, int HW)
{
    const float* p = in + (size_t)blockIdx.x * HW;
    float s = 0.0f;
    for (int i = threadIdx.x; i < HW; i += blockDim.x) s += p[i];
    __shared__ float sm[256];
    sm[threadIdx.x] = s;
    __syncthreads();
    for (int st = 128; st > 0; st >>= 1) {
        if (threadIdx.x < st) sm[threadIdx.x] += sm[threadIdx.x + st];
        __syncthreads();
    }
    if (threadIdx.x == 0) out[blockIdx.x] = sm[0] / (float)HW;
}

// ---------------------------------------------------------------------------
// Launch pipeline (graph-capturable: kernel launches + attribute sets only).
// ---------------------------------------------------------------------------
static inline int conv_smem_bytes(int stride, int th)
{
    int tih  = th * stride + 2;
    int tiwp = (32 * stride + 5 + 3) & ~3;
    int tile_n = 8 * tih * tiwp;
    return (2 * tile_n + 2 * (32 * 76)) * 4;   // 45056 (s1,TH8) / 65536 (s2,TH4)
}

extern "C" void kernel_launch(void* const* d_in, const int* in_sizes, int n_in,
                              void* d_out, int out_size)
{
    const float* x   = (const float*)d_in[0];
    const float* w1  = (const float*)d_in[1];
    const float* b1  = (const float*)d_in[2];
    const float* ow1 = (const float*)d_in[3];
    const float* w2  = (const float*)d_in[4];
    const float* b2  = (const float*)d_in[5];
    const float* ow2 = (const float*)d_in[6];
    const float* w3  = (const float*)d_in[7];
    const float* b3  = (const float*)d_in[8];
    const float* ow3 = (const float*)d_in[9];
    const float* w4  = (const float*)d_in[10];
    const float* b4  = (const float*)d_in[11];
    float* outp = (float*)d_out;

    float *A, *B, *C, *WT;
    cudaGetSymbolAddress((void**)&A, g_bufA);
    cudaGetSymbolAddress((void**)&B, g_bufB);
    cudaGetSymbolAddress((void**)&C, g_bufC);
    cudaGetSymbolAddress((void**)&WT, g_wt);

    const int S1 = conv_smem_bytes(1, 8), S2 = conv_smem_bytes(2, 4);
    cudaFuncSetAttribute(conv3x3_tc<1, 32, 1, 8>, cudaFuncAttributeMaxDynamicSharedMemorySize, S1);
    cudaFuncSetAttribute(conv3x3_tc<1, 32, 0, 8>, cudaFuncAttributeMaxDynamicSharedMemorySize, S1);
    cudaFuncSetAttribute(conv3x3_tc<1, 64, 0, 8>, cudaFuncAttributeMaxDynamicSharedMemorySize, S1);
    cudaFuncSetAttribute(conv3x3_tc<2, 32, 1, 4>, cudaFuncAttributeMaxDynamicSharedMemorySize, S2);
    cudaFuncSetAttribute(conv3x3_tc<2, 64, 1, 4>, cudaFuncAttributeMaxDynamicSharedMemorySize, S2);

    // Preprocessed weights (concatenated in g_wt, same order as PrepDesc).
    float* w1t  = WT;             // 9216
    float* ow1t = WT + 9216;      // 18432
    float* w2t  = WT + 27648;     // 18432
    float* ow2t = WT + 46080;     // 73728
    float* w3t  = WT + 119808;    // 18432
    float* ow3t = WT + 138240;    // 18432
    float* w4t  = WT + 156672;    // 9216

    {
        PrepDesc d;
        d.src[0] = w1;  d.cin[0] = 32;
        d.src[1] = ow1; d.cin[1] = 32;
        d.src[2] = w2;  d.cin[2] = 32;
        d.src[3] = ow2; d.cin[3] = 64;
        d.src[4] = w3;  d.cin[4] = 64;
        d.src[5] = ow3; d.cin[5] = 32;
        d.src[6] = w4;  d.cin[6] = 32;
        d.off[0] = 0;      d.off[1] = 9216;   d.off[2] = 27648;
        d.off[3] = 46080;  d.off[4] = 119808; d.off[5] = 138240;
        d.off[6] = 156672; d.off[7] = 165888;
        prep_all<<<(165888 + 255) / 256, 256>>>(d, WT);
    }
    {
        int n4 = 16 * 32 * 256 * 256 / 4;
        cvt4_kernel<<<(n4 + 255) / 256, 256>>>((const float4*)x, (float4*)C, n4);
    }

    // 1) conv1: C(x~) -> A (16,32,256,256), bias+relu
    conv3x3_tc<1, 32, 1, 8><<<dim3(8, 32, 16), 256, S1>>>(C, w1t, b1, A, 32, 256, 256);

    // 2) offconv1: A -> B (16,64,256,256)
    conv3x3_tc<1, 32, 0, 8><<<dim3(8, 32, 32), 256, S1>>>(A, ow1t, nullptr, B, 64, 256, 256);

    // 3) deform1: A,B -> C (16,32,256,256)
    {
        int total = 16 * 32 * 256 * 256;
        deform_kernel<<<total / 256, 256>>>(A, B, C, 8, 8, 5, total);
    }

    // 4) conv2 stride2: C -> A (16,64,128,128), bias+relu
    conv3x3_tc<2, 32, 1, 4><<<dim3(4, 32, 32), 256, S2>>>(C, w2t, b2, A, 64, 256, 256);

    // 5) offconv2: A -> B (16,128,128,128)
    conv3x3_tc<1, 64, 0, 8><<<dim3(4, 16, 64), 256, S1>>>(A, ow2t, nullptr, B, 128, 128, 128);

    // 6) deform2: A,B -> C (16,64,128,128)
    {
        int total = 16 * 64 * 128 * 128;
        deform_kernel<<<total / 256, 256>>>(A, B, C, 7, 7, 6, total);
    }

    // 7) conv3 stride2: C -> A (16,32,64,64), bias+relu
    conv3x3_tc<2, 64, 1, 4><<<dim3(2, 16, 16), 256, S2>>>(C, w3t, b3, A, 32, 128, 128);

    // 8) offconv3: A -> B (16,64,64,64)
    conv3x3_tc<1, 32, 0, 8><<<dim3(2, 8, 32), 256, S1>>>(A, ow3t, nullptr, B, 64, 64, 64);

    // 9) deform3: A,B -> C (16,32,64,64)
    {
        int total = 16 * 32 * 64 * 64;
        deform_kernel<<<total / 256, 256>>>(A, B, C, 6, 6, 5, total);
    }

    // 10) conv4 stride2: C -> A (16,32,32,32), bias+relu
    conv3x3_tc<2, 32, 1, 4><<<dim3(1, 8, 16), 256, S2>>>(C, w4t, b4, A, 32, 64, 64);

    // 11) global avg pool -> (16,32,1,1)
    avgpool_kernel<<<512, 256>>>(A, outp, 32 * 32);
}

// round 8
// speedup vs baseline: 2.5712x; 2.1488x over previous
#include <cuda_runtime.h>
#include <cuda_fp16.h>
#include <cstdint>

// ---------------------------------------------------------------------------
// Scratch buffers (static __device__ globals — no allocation allowed).
// Activations live here as channel-pair-interleaved half2 (viewed as u32).
// ---------------------------------------------------------------------------
__device__ float g_bufA[33554432];
__device__ float g_bufB[67108864];
__device__ float g_bufC[33554432];
__device__ float g_wt[262144];          // prepacked half2 weights (u32 view)

// ---------------------------------------------------------------------------
// Helpers
// ---------------------------------------------------------------------------
__device__ __forceinline__ uint32_t packh2(float lo, float hi)
{
    __half2 h = __floats2half2_rn(lo, hi);   // .x = lo = low 16 bits
    return *reinterpret_cast<uint32_t*>(&h);
}

__device__ __forceinline__ float unpackh(uint32_t u, int parity)
{
    __half2 h = *reinterpret_cast<__half2*>(&u);
    return __half2float(parity ? __high2half(h) : __low2half(h));
}

__device__ __forceinline__ void mma_f16(float* c,
                                        uint32_t a0, uint32_t a1,
                                        uint32_t a2, uint32_t a3,
                                        uint32_t b0, uint32_t b1)
{
    asm volatile(
        "mma.sync.aligned.m16n8k16.row.col.f32.f16.f16.f32 "
        "{%0,%1,%2,%3}, {%4,%5,%6,%7}, {%8,%9}, {%0,%1,%2,%3};\n"
        : "+f"(c[0]), "+f"(c[1]), "+f"(c[2]), "+f"(c[3])
        : "r"(a0), "r"(a1), "r"(a2), "r"(a3), "r"(b0), "r"(b1));
}

__device__ __forceinline__ uint32_t smem_u32(const void* p)
{
    return (uint32_t)__cvta_generic_to_shared(p);
}

// 16B cp.async; src-size 0 -> 16 zero bytes written (halo padding).
__device__ __forceinline__ void cp16z(uint32_t dst, const void* src, bool ok)
{
    int sz = ok ? 16 : 0;
    asm volatile("cp.async.ca.shared.global [%0], [%1], 16, %2;"
                 :: "r"(dst), "l"(src), "r"(sz));
}

// ---------------------------------------------------------------------------
// Implicit-GEMM 3x3 conv (pad=1), fp16 mma.sync.m16n8k16, f32 accumulate,
// cp.async double-buffered pipeline. All activations are channel-pair-
// interleaved half2 (one u32 per pixel per channel pair).
//
// K order: k = r*16 + cipair*2 + parity (r = dy*3+dx). So each k16 step is
// one kernel tap r; B fragment regs b0/b1 = tile[cipair=tig / tig+4] at the
// tap's pixel — a single u32 LDS each carrying 2 k-values.
// Output tile: 32 couts x (TH h x 32 w), 256 thr.
//   TH=8 (stride-1): warp = one row; M=2 co-tiles, B frags reused.
//   TH=4 (stride-2): warp = (co half, row); M=1.
// WSTR=72 -> A LDS.64 conflict-free; CHEP ≡ 8 (mod 32) -> stride-1 B loads
// conflict-free.
// ---------------------------------------------------------------------------
template<int STRIDE, int CIN, int BR, int TH>
__global__ __launch_bounds__(256, 2)
void conv3x3_h(const uint32_t* __restrict__ in, const uint32_t* __restrict__ w,
               const float* __restrict__ bias, uint32_t* __restrict__ out,
               int Cout, int Hin, int Win)
{
    constexpr int TW = 32;
    constexpr int M    = (TH == 8) ? 2 : 1;
    constexpr int TIH  = TH * STRIDE + 2;               // 10 / 10
    constexpr int TIWP = (TW * STRIDE + 5 + 3) & ~3;    // 40 / 72 (pixels=u32)
    constexpr int RU   = TIWP / 4;                      // 16B units per row
    constexpr int CHE  = TIH * TIWP;
    constexpr int CHEP = ((CHE + 8 + 31) & ~31) | 8;    // ≡8 mod 32 (424/744)
    constexpr int TILE_N = 8 * CHEP;                    // u32 per tile buffer
    constexpr int NCH  = CIN / 16;                      // 16 ci per chunk
    constexpr int WSTR = 72;                            // u32 per co
    constexpr int WN   = 32 * WSTR;                     // 2304 u32
    constexpr int TU   = 8 * TIH * RU;
    constexpr int WU   = WN / 4;                        // 576 16B units

    extern __shared__ __align__(16) uint32_t smem[];    // [tile0|tile1|w0|w1]
    __shared__ int s_koff[72];

    const int Hout = Hin / STRIDE, Wout = Win / STRIDE;
    const int tid = threadIdx.x;
    const int groups = Cout >> 5;
    const int g  = blockIdx.z % groups;
    const int b  = blockIdx.z / groups;
    const int bx = blockIdx.x, by = blockIdx.y;

    if (tid < 72) {
        int r = tid >> 3, j = tid & 7;
        s_koff[tid] = j * CHEP + (r / 3) * TIWP + (r % 3);
    }

    const int y0 = by * TH * STRIDE - 1;
    const int x0 = bx * TW * STRIDE - 4;    // 16B-aligned halo (logical -1 = col 3)
    const size_t HW = (size_t)Hin * Win;    // u32 per channel pair
    const uint32_t* ibase = in + (size_t)b * (CIN / 2) * HW;
    const uint32_t* wbase = w + (size_t)g * NCH * WN;

    const uint32_t tile_s = smem_u32(smem);
    const uint32_t wbuf_s = smem_u32(smem + 2 * TILE_N);

    auto load_chunk = [&](int ch, int bi) {
        const uint32_t* isrc = ibase + (size_t)(ch * 8) * HW;
        uint32_t td = tile_s + (bi ? 4u * TILE_N : 0u);
        #pragma unroll 4
        for (int u = tid; u < TU; u += 256) {
            int cp8 = u / (TIH * RU);
            int rem = u - cp8 * (TIH * RU);
            int r = rem / RU, uu = rem - r * RU;
            int gy = y0 + r, gx = x0 + 4 * uu;
            bool ok = (gy >= 0) && (gy < Hin) && (gx >= 0) && (gx < Win);
            cp16z(td + 4u * (uint32_t)(cp8 * CHEP + r * TIWP + 4 * uu),
                  isrc + (size_t)cp8 * HW + (size_t)gy * Win + gx, ok);
        }
        const uint32_t* wsrc = wbase + ch * WN;
        uint32_t wd = wbuf_s + (bi ? 4u * WN : 0u);
        #pragma unroll 3
        for (int u = tid; u < WU; u += 256)
            cp16z(wd + 16u * (uint32_t)u, wsrc + 4 * u, true);
        asm volatile("cp.async.commit_group;");
    };

    const int lane = tid & 31, wid = tid >> 5;
    const int tig = lane & 3, gid = lane >> 2;
    const int mh = (TH == 8) ? 0 : (wid & 1);
    const int nq = (TH == 8) ? wid : (wid >> 1);

    float acc[M][4][4];
    #pragma unroll
    for (int m = 0; m < M; m++) {
        const int cb = (TH == 8) ? m * 16 : mh * 16;
        float bv0 = 0.0f, bv1 = 0.0f;
        if (BR) {
            bv0 = bias[g * 32 + cb + gid];
            bv1 = bias[g * 32 + cb + gid + 8];
        }
        #pragma unroll
        for (int t = 0; t < 4; t++) {
            acc[m][t][0] = bv0; acc[m][t][1] = bv0;
            acc[m][t][2] = bv1; acc[m][t][3] = bv1;
        }
    }

    load_chunk(0, 0);

    #pragma unroll
    for (int ch = 0; ch < NCH; ch++) {
        const int cur = ch & 1;
        if (ch + 1 < NCH) {
            load_chunk(ch + 1, cur ^ 1);
            asm volatile("cp.async.wait_group 1;");
        } else {
            asm volatile("cp.async.wait_group 0;");
        }
        __syncthreads();

        const uint32_t* st = smem + cur * TILE_N;
        const uint32_t* sw = smem + 2 * TILE_N + cur * WN;
        const int bb = nq * STRIDE * TIWP + gid * STRIDE + 3;

        #pragma unroll
        for (int ks = 0; ks < 9; ks++) {
            const int ko1 = s_koff[ks * 8 + tig];
            const int ko2 = s_koff[ks * 8 + tig + 4];
            uint32_t a0[M], a1[M], a2[M], a3[M];
            #pragma unroll
            for (int m = 0; m < M; m++) {
                const int cb = (TH == 8) ? m * 16 : mh * 16;
                const uint32_t* ap = sw + (cb + gid) * WSTR + ks * 8 + 2 * tig;
                uint2 lo = *reinterpret_cast<const uint2*>(ap);            // a0,a2
                uint2 hi = *reinterpret_cast<const uint2*>(ap + 8 * WSTR); // a1,a3
                a0[m] = lo.x; a2[m] = lo.y;
                a1[m] = hi.x; a3[m] = hi.y;
            }
            #pragma unroll
            for (int t = 0; t < 4; t++) {
                uint32_t b0 = st[ko1 + bb + t * 8 * STRIDE];
                uint32_t b1 = st[ko2 + bb + t * 8 * STRIDE];
                #pragma unroll
                for (int m = 0; m < M; m++)
                    mma_f16(acc[m][t], a0[m], a1[m], a2[m], a3[m], b0, b1);
            }
        }
        __syncthreads();
    }

    // Epilogue: pair up (even, odd) co via shfl_xor(4), store half2 (u32x2).
    const int hrow = by * TH + nq;
    const size_t HWo = (size_t)Hout * Wout;
    #pragma unroll
    for (int m = 0; m < M; m++) {
        const int cb = (TH == 8) ? m * 16 : mh * 16;
        const int cbg = g * 32 + cb;
        #pragma unroll
        for (int t = 0; t < 4; t++) {
            float v0 = acc[m][t][0], v1 = acc[m][t][1];
            float v2 = acc[m][t][2], v3 = acc[m][t][3];
            if (BR) {
                v0 = fmaxf(v0, 0.0f); v1 = fmaxf(v1, 0.0f);
                v2 = fmaxf(v2, 0.0f); v3 = fmaxf(v3, 0.0f);
            }
            float p0 = __shfl_xor_sync(0xffffffffu, v0, 4);
            float p1 = __shfl_xor_sync(0xffffffffu, v1, 4);
            float p2 = __shfl_xor_sync(0xffffffffu, v2, 4);
            float p3 = __shfl_xor_sync(0xffffffffu, v3, 4);
            const int wg = bx * 32 + t * 8 + 2 * tig;
            uint2 st2;
            int copair;
            if ((gid & 1) == 0) {
                // own rows gid (even co), partner rows gid+1 (odd co)
                st2.x = packh2(v0, p0);
                st2.y = packh2(v1, p1);
                copair = (cbg + gid) >> 1;
            } else {
                // rows gid+8 (odd co), partner rows gid+7 (even co)
                st2.x = packh2(p2, v2);
                st2.y = packh2(p3, v3);
                copair = (cbg + gid + 7) >> 1;
            }
            *reinterpret_cast<uint2*>(
                out + ((size_t)b * (Cout / 2) + copair) * HWo
                    + (size_t)hrow * Wout + wg) = st2;
        }
    }
}

// ---------------------------------------------------------------------------
// ConvOffset2D bilinear sampling on interleaved-half2 buffers.
// Faithful torch raw-reshape: o0/o1 live at flat indices (2G, 2G+1) of the
// NCHW offconv output; mapped into the interleaved layout via exact index
// arithmetic. Each thread produces one output channel PAIR at one pixel.
// ---------------------------------------------------------------------------
__global__ void deform_h(const uint32_t* __restrict__ x,
                         const uint32_t* __restrict__ off,
                         uint32_t* __restrict__ out,
                         int wsh, int hsh, int csh, int total_pairs)
{
    int idx = blockIdx.x * 256 + threadIdx.x;
    if (idx >= total_pairs) return;
    const int W = 1 << wsh, H = 1 << hsh;
    const int sh2 = wsh + hsh;
    const unsigned HW = 1u << sh2;
    const int C = 1 << csh;

    int p = idx & (HW - 1);
    int cpair = (idx >> sh2) & ((1 << (csh - 1)) - 1);
    int b = idx >> (sh2 + csh - 1);
    int h = p >> wsh, wcol = p & (W - 1);

    const uint32_t* xb = x + (size_t)b * (C / 2) * HW;
    const uint32_t* ob = off + (size_t)b * C * HW;   // off has 2C chans = C pairs

    float res[2];
    #pragma unroll
    for (int par = 0; par < 2; par++) {
        int c = 2 * cpair + par;
        unsigned G = (unsigned)c * HW + (unsigned)p;
        unsigned F0 = 2u * G, F1 = 2u * G + 1u;
        unsigned co0 = F0 >> sh2, pp0 = F0 & (HW - 1);
        unsigned co1 = F1 >> sh2, pp1 = F1 & (HW - 1);
        float o0 = unpackh(ob[(size_t)(co0 >> 1) * HW + pp0], co0 & 1);
        float o1 = unpackh(ob[(size_t)(co1 >> 1) * HW + pp1], co1 & 1);

        float r  = fminf(fmaxf(o0 + (float)h,    0.0f), (float)(H - 1));
        float cc = fminf(fmaxf(o1 + (float)wcol, 0.0f), (float)(W - 1));
        float r0f = floorf(r), c0f = floorf(cc);
        int r0 = (int)r0f, r1 = (int)ceilf(r);
        int c0 = (int)c0f, c1 = (int)ceilf(cc);

        const uint32_t* xp = xb + (size_t)cpair * HW;
        float vlt = unpackh(xp[(r0 << wsh) + c0], par);
        float vrb = unpackh(xp[(r1 << wsh) + c1], par);
        float vlb = unpackh(xp[(r0 << wsh) + c1], par);
        float vrt = unpackh(xp[(r1 << wsh) + c0], par);
        float fr = r - r0f, fc = cc - c0f;
        float vt = vlt + (vrt - vlt) * fr;
        float vb = vlb + (vrb - vlb) * fr;
        res[par] = vt + (vb - vt) * fc;
    }
    out[idx] = packh2(res[0], res[1]);
}

// ---------------------------------------------------------------------------
// Weight prepass (ONE launch): all 7 tensors -> half2, layout
// [g][ch(16ci)][co32][ks(9)][e(8)] where e=2*tig+s -> cipair = s?tig+4:tig,
// half2 = (W[ci even], W[ci odd]) at tap ks.
// ---------------------------------------------------------------------------
struct PrepDesc {
    const float* src[7];
    int cin[7];
    int off[8];         // prefix sums in u32 elements
};

__global__ void prep_all_h(PrepDesc d, uint32_t* __restrict__ dst)
{
    int i = blockIdx.x * 256 + threadIdx.x;
    if (i >= d.off[7]) return;
    int s = 0;
    #pragma unroll
    for (int k = 0; k < 6; k++) s += (i >= d.off[k + 1]) ? 1 : 0;
    int j = i - d.off[s];
    const int CIN = d.cin[s];
    const int NCH = CIN >> 4;

    int e  = j & 7;
    int ks = (j >> 3) % 9;
    int rest = j / 72;
    int co = rest & 31; rest >>= 5;
    int ch = rest % NCH;
    int gi = rest / NCH;
    int cipair = (e & 1) ? (e >> 1) + 4 : (e >> 1);
    int ci = ch * 16 + cipair * 2;
    const float* sp = d.src[s] + (((size_t)(gi * 32 + co)) * CIN + ci) * 9 + ks;
    dst[i] = packh2(sp[0], sp[9]);
}

// ---------------------------------------------------------------------------
// x prepass: NCHW f32 -> interleaved half2 (vectorized 4 px/thread).
// ---------------------------------------------------------------------------
__global__ void cvt_x4(const float4* __restrict__ src, uint4* __restrict__ dst,
                       int sh2m2, int total4)
{
    int i = blockIdx.x * 256 + threadIdx.x;
    if (i >= total4) return;
    int poff = i & ((1 << sh2m2) - 1);
    int pair = i >> sh2m2;
    float4 a = src[(((size_t)pair * 2)     << sh2m2) + poff];
    float4 c = src[(((size_t)pair * 2 + 1) << sh2m2) + poff];
    dst[i] = make_uint4(packh2(a.x, c.x), packh2(a.y, c.y),
                        packh2(a.z, c.z), packh2(a.w, c.w));
}

// ---------------------------------------------------------------------------
// Global average pool from interleaved half2. One block per channel pair.
// ---------------------------------------------------------------------------
__global__ void avgpool_h(const uint32_t* __restrict__ in,
                          float* __restrict__ out, int HW, int halfC)
{
    const uint32_t* p = in + (size_t)blockIdx.x * HW;
    float lo = 0.0f, hi = 0.0f;
    for (int i = threadIdx.x; i < HW; i += 256) {
        float2 f = __half22float2(*reinterpret_cast<const __half2*>(p + i));
        lo += f.x; hi += f.y;
    }
    __shared__ float smlo[256], smhi[256];
    smlo[threadIdx.x] = lo; smhi[threadIdx.x] = hi;
    __syncthreads();
    for (int st = 128; st > 0; st >>= 1) {
        if (threadIdx.x < st) {
            smlo[threadIdx.x] += smlo[threadIdx.x + st];
            smhi[threadIdx.x] += smhi[threadIdx.x + st];
        }
        __syncthreads();
    }
    if (threadIdx.x == 0) {
        int b = blockIdx.x / halfC, cp = blockIdx.x % halfC;
        out[b * 2 * halfC + 2 * cp]     = smlo[0] / (float)HW;
        out[b * 2 * halfC + 2 * cp + 1] = smhi[0] / (float)HW;
    }
}

// ---------------------------------------------------------------------------
// Launch pipeline (graph-capturable: kernel launches + attribute sets only).
// ---------------------------------------------------------------------------
static inline int conv_smem_bytes(int stride, int th)
{
    int tih  = th * stride + 2;
    int tiwp = (32 * stride + 5 + 3) & ~3;
    int che  = tih * tiwp;
    int chep = ((che + 8 + 31) & ~31) | 8;
    int tile_n = 8 * chep;
    return (2 * tile_n + 2 * (32 * 72)) * 4;   // 45568 (s1) / 66048 (s2)
}

extern "C" void kernel_launch(void* const* d_in, const int* in_sizes, int n_in,
                              void* d_out, int out_size)
{
    const float* x   = (const float*)d_in[0];
    const float* w1  = (const float*)d_in[1];
    const float* b1  = (const float*)d_in[2];
    const float* ow1 = (const float*)d_in[3];
    const float* w2  = (const float*)d_in[4];
    const float* b2  = (const float*)d_in[5];
    const float* ow2 = (const float*)d_in[6];
    const float* w3  = (const float*)d_in[7];
    const float* b3  = (const float*)d_in[8];
    const float* ow3 = (const float*)d_in[9];
    const float* w4  = (const float*)d_in[10];
    const float* b4  = (const float*)d_in[11];
    float* outp = (float*)d_out;

    float *Af, *Bf, *Cf, *WTf;
    cudaGetSymbolAddress((void**)&Af, g_bufA);
    cudaGetSymbolAddress((void**)&Bf, g_bufB);
    cudaGetSymbolAddress((void**)&Cf, g_bufC);
    cudaGetSymbolAddress((void**)&WTf, g_wt);
    uint32_t* A  = (uint32_t*)Af;
    uint32_t* B  = (uint32_t*)Bf;
    uint32_t* C  = (uint32_t*)Cf;
    uint32_t* WT = (uint32_t*)WTf;

    const int S1 = conv_smem_bytes(1, 8), S2 = conv_smem_bytes(2, 4);
    cudaFuncSetAttribute(conv3x3_h<1, 32, 1, 8>, cudaFuncAttributeMaxDynamicSharedMemorySize, S1);
    cudaFuncSetAttribute(conv3x3_h<1, 32, 0, 8>, cudaFuncAttributeMaxDynamicSharedMemorySize, S1);
    cudaFuncSetAttribute(conv3x3_h<1, 64, 0, 8>, cudaFuncAttributeMaxDynamicSharedMemorySize, S1);
    cudaFuncSetAttribute(conv3x3_h<2, 32, 1, 4>, cudaFuncAttributeMaxDynamicSharedMemorySize, S2);
    cudaFuncSetAttribute(conv3x3_h<2, 64, 1, 4>, cudaFuncAttributeMaxDynamicSharedMemorySize, S2);

    // Prepacked weights (u32 offsets): w1 4608 | ow1 9216 | w2 9216 |
    // ow2 36864 | w3 9216 | ow3 9216 | w4 4608
    uint32_t* w1t  = WT;
    uint32_t* ow1t = WT + 4608;
    uint32_t* w2t  = WT + 13824;
    uint32_t* ow2t = WT + 23040;
    uint32_t* w3t  = WT + 59904;
    uint32_t* ow3t = WT + 69120;
    uint32_t* w4t  = WT + 78336;

    {
        PrepDesc d;
        d.src[0] = w1;  d.cin[0] = 32;
        d.src[1] = ow1; d.cin[1] = 32;
        d.src[2] = w2;  d.cin[2] = 32;
        d.src[3] = ow2; d.cin[3] = 64;
        d.src[4] = w3;  d.cin[4] = 64;
        d.src[5] = ow3; d.cin[5] = 32;
        d.src[6] = w4;  d.cin[6] = 32;
        d.off[0] = 0;     d.off[1] = 4608;  d.off[2] = 13824;
        d.off[3] = 23040; d.off[4] = 59904; d.off[5] = 69120;
        d.off[6] = 78336; d.off[7] = 82944;
        prep_all_h<<<(82944 + 255) / 256, 256>>>(d, WT);
    }
    {
        // x (16,32,256,256) f32 -> interleaved half2 in C
        int total4 = 16 * 16 * 65536 / 4;   // u32 count / 4
        cvt_x4<<<(total4 + 255) / 256, 256>>>((const float4*)x, (uint4*)C, 14, total4);
    }

    // 1) conv1: C(x~) -> A (16,32,256,256), bias+relu
    conv3x3_h<1, 32, 1, 8><<<dim3(8, 32, 16), 256, S1>>>(C, w1t, b1, A, 32, 256, 256);

    // 2) offconv1: A -> B (16,64,256,256)
    conv3x3_h<1, 32, 0, 8><<<dim3(8, 32, 32), 256, S1>>>(A, ow1t, nullptr, B, 64, 256, 256);

    // 3) deform1: A,B -> C (16,32,256,256) ; 16*16*65536 pairs
    deform_h<<<65536, 256>>>(A, B, C, 8, 8, 5, 16 * 16 * 65536);

    // 4) conv2 stride2: C -> A (16,64,128,128), bias+relu
    conv3x3_h<2, 32, 1, 4><<<dim3(4, 32, 32), 256, S2>>>(C, w2t, b2, A, 64, 256, 256);

    // 5) offconv2: A -> B (16,128,128,128)
    conv3x3_h<1, 64, 0, 8><<<dim3(4, 16, 64), 256, S1>>>(A, ow2t, nullptr, B, 128, 128, 128);

    // 6) deform2: A,B -> C (16,64,128,128) ; 16*32*16384 pairs
    deform_h<<<32768, 256>>>(A, B, C, 7, 7, 6, 16 * 32 * 16384);

    // 7) conv3 stride2: C -> A (16,32,64,64), bias+relu
    conv3x3_h<2, 64, 1, 4><<<dim3(2, 16, 16), 256, S2>>>(C, w3t, b3, A, 32, 128, 128);

    // 8) offconv3: A -> B (16,64,64,64)
    conv3x3_h<1, 32, 0, 8><<<dim3(2, 8, 32), 256, S1>>>(A, ow3t, nullptr, B, 64, 64, 64);

    // 9) deform3: A,B -> C (16,32,64,64) ; 16*16*4096 pairs
    deform_h<<<4096, 256>>>(A, B, C, 6, 6, 5, 16 * 16 * 4096);

    // 10) conv4 stride2: C -> A (16,32,32,32), bias+relu
    conv3x3_h<2, 32, 1, 4><<<dim3(1, 8, 16), 256, S2>>>(C, w4t, b4, A, 32, 64, 64);

    // 11) global avg pool: A (interleaved) -> out f32 (16,32,1,1)
    avgpool_h<<<256, 256>>>(A, outp, 1024, 16);
}

// round 9
// speedup vs baseline: 2.8264x; 1.0993x over previous
#include <cuda_runtime.h>
#include <cuda_fp16.h>
#include <cstdint>

// ---------------------------------------------------------------------------
// Scratch buffers (static __device__ globals — no allocation allowed).
// Activations live here as channel-pair-interleaved half2 (viewed as u32).
// ---------------------------------------------------------------------------
__device__ float g_bufA[33554432];
__device__ float g_bufB[67108864];
__device__ float g_bufC[33554432];
__device__ float g_wt[262144];          // prepacked half2 weights (u32 view)

// ---------------------------------------------------------------------------
// Helpers
// ---------------------------------------------------------------------------
__device__ __forceinline__ uint32_t packh2(float lo, float hi)
{
    __half2 h = __floats2half2_rn(lo, hi);   // .x = lo = low 16 bits
    return *reinterpret_cast<uint32_t*>(&h);
}

__device__ __forceinline__ float unpackh(uint32_t u, int parity)
{
    __half2 h = *reinterpret_cast<__half2*>(&u);
    return __half2float(parity ? __high2half(h) : __low2half(h));
}

__device__ __forceinline__ void mma_f16(float* c,
                                        uint32_t a0, uint32_t a1,
                                        uint32_t a2, uint32_t a3,
                                        uint32_t b0, uint32_t b1)
{
    asm volatile(
        "mma.sync.aligned.m16n8k16.row.col.f32.f16.f16.f32 "
        "{%0,%1,%2,%3}, {%4,%5,%6,%7}, {%8,%9}, {%0,%1,%2,%3};\n"
        : "+f"(c[0]), "+f"(c[1]), "+f"(c[2]), "+f"(c[3])
        : "r"(a0), "r"(a1), "r"(a2), "r"(a3), "r"(b0), "r"(b1));
}

__device__ __forceinline__ uint32_t smem_u32(const void* p)
{
    return (uint32_t)__cvta_generic_to_shared(p);
}

// 16B cp.async; src-size 0 -> 16 zero bytes written (halo padding).
__device__ __forceinline__ void cp16z(uint32_t dst, const void* src, bool ok)
{
    int sz = ok ? 16 : 0;
    asm volatile("cp.async.ca.shared.global [%0], [%1], 16, %2;"
                 :: "r"(dst), "l"(src), "r"(sz));
}

// ---------------------------------------------------------------------------
// Implicit-GEMM 3x3 conv (pad=1), fp16 mma.sync.m16n8k16, f32 accumulate,
// cp.async double-buffered pipeline. Activations channel-pair-interleaved
// half2 (one u32 per pixel per channel pair).
//
// K order: k = r*16 + cipair*2 + parity (r = dy*3+dx). Each k16 step = one
// kernel tap r; B fragment regs are single u32 LDS (2 k-values each), with
// fully compile-time tap offsets: addr = tig*CHEP + bb + KO(ks) + t*8*STRIDE
// (KO folded into LDS immediates — no index table, minimal IMAD).
// Output tile: 32 couts x (TH h x 32 w), 256 thr.
//   TH=8 (stride-1): warp = one row; M=2 co-tiles, B frags reused.
//   TH=4 (stride-2): warp = (co half, row); M=1.
// WSTR=72 -> A LDS.64 conflict-free; CHEP ≡ 8 (mod 32) -> stride-1 B loads
// conflict-free.
// ---------------------------------------------------------------------------
template<int STRIDE, int CIN, int BR, int TH>
__global__ __launch_bounds__(256, 3)
void conv3x3_h(const uint32_t* __restrict__ in, const uint32_t* __restrict__ w,
               const float* __restrict__ bias, uint32_t* __restrict__ out,
               int Cout, int Hin, int Win)
{
    constexpr int TW = 32;
    constexpr int M    = (TH == 8) ? 2 : 1;
    constexpr int TIH  = TH * STRIDE + 2;               // 10 / 10
    constexpr int TIWP = (TW * STRIDE + 5 + 3) & ~3;    // 40 / 72 (pixels=u32)
    constexpr int RU   = TIWP / 4;                      // 16B units per row
    constexpr int CHE  = TIH * TIWP;
    constexpr int CHEP = ((CHE + 8 + 31) & ~31) | 8;    // ≡8 mod 32 (424/744)
    constexpr int TILE_N = 8 * CHEP;                    // u32 per tile buffer
    constexpr int NCH  = CIN / 16;                      // 16 ci per chunk
    constexpr int WSTR = 72;                            // u32 per co
    constexpr int WN   = 32 * WSTR;                     // 2304 u32
    constexpr int TU   = 8 * TIH * RU;
    constexpr int WU   = WN / 4;                        // 576 16B units

    extern __shared__ __align__(16) uint32_t smem[];    // [tile0|tile1|w0|w1]

    const int Hout = Hin / STRIDE, Wout = Win / STRIDE;
    const int tid = threadIdx.x;
    const int groups = Cout >> 5;
    const int g  = blockIdx.z % groups;
    const int b  = blockIdx.z / groups;
    const int bx = blockIdx.x, by = blockIdx.y;

    const int y0 = by * TH * STRIDE - 1;
    const int x0 = bx * TW * STRIDE - 4;    // 16B-aligned halo (logical -1 = col 3)
    const size_t HW = (size_t)Hin * Win;    // u32 per channel pair
    const uint32_t* ibase = in + (size_t)b * (CIN / 2) * HW;
    const uint32_t* wbase = w + (size_t)g * NCH * WN;

    const uint32_t tile_s = smem_u32(smem);
    const uint32_t wbuf_s = smem_u32(smem + 2 * TILE_N);

    auto load_chunk = [&](int ch, int bi) {
        const uint32_t* isrc = ibase + (size_t)(ch * 8) * HW;
        uint32_t td = tile_s + (bi ? 4u * TILE_N : 0u);
        #pragma unroll 4
        for (int u = tid; u < TU; u += 256) {
            int cp8 = u / (TIH * RU);
            int rem = u - cp8 * (TIH * RU);
            int r = rem / RU, uu = rem - r * RU;
            int gy = y0 + r, gx = x0 + 4 * uu;
            bool ok = (gy >= 0) && (gy < Hin) && (gx >= 0) && (gx < Win);
            cp16z(td + 4u * (uint32_t)(cp8 * CHEP + r * TIWP + 4 * uu),
                  isrc + (size_t)cp8 * HW + (size_t)gy * Win + gx, ok);
        }
        const uint32_t* wsrc = wbase + ch * WN;
        uint32_t wd = wbuf_s + (bi ? 4u * WN : 0u);
        #pragma unroll 3
        for (int u = tid; u < WU; u += 256)
            cp16z(wd + 16u * (uint32_t)u, wsrc + 4 * u, true);
        asm volatile("cp.async.commit_group;");
    };

    const int lane = tid & 31, wid = tid >> 5;
    const int tig = lane & 3, gid = lane >> 2;
    const int mh = (TH == 8) ? 0 : (wid & 1);
    const int nq = (TH == 8) ? wid : (wid >> 1);

    float acc[M][4][4];
    #pragma unroll
    for (int m = 0; m < M; m++) {
        const int cb = (TH == 8) ? m * 16 : mh * 16;
        float bv0 = 0.0f, bv1 = 0.0f;
        if (BR) {
            bv0 = bias[g * 32 + cb + gid];
            bv1 = bias[g * 32 + cb + gid + 8];
        }
        #pragma unroll
        for (int t = 0; t < 4; t++) {
            acc[m][t][0] = bv0; acc[m][t][1] = bv0;
            acc[m][t][2] = bv1; acc[m][t][3] = bv1;
        }
    }

    load_chunk(0, 0);

    #pragma unroll
    for (int ch = 0; ch < NCH; ch++) {
        const int cur = ch & 1;
        if (ch + 1 < NCH) {
            load_chunk(ch + 1, cur ^ 1);
            asm volatile("cp.async.wait_group 1;");
        } else {
            asm volatile("cp.async.wait_group 0;");
        }
        __syncthreads();

        const uint32_t* st = smem + cur * TILE_N;
        const uint32_t* sw = smem + 2 * TILE_N + cur * WN;
        // Register bases; all tap/pixel offsets below are compile-time
        // immediates folded into the LDS instructions.
        const uint32_t* bp1 = st + tig * CHEP + nq * STRIDE * TIWP + gid * STRIDE + 3;
        const uint32_t* bp2 = bp1 + 4 * CHEP;
        const uint32_t* ap0 = sw + gid * WSTR + 2 * tig;
        const uint32_t* ap1 = sw + ((TH == 8 ? 16 : mh * 16) + gid) * WSTR + 2 * tig;
        if (TH != 8) ap0 = ap1;   // M=1: single co-tile at mh*16

        #pragma unroll
        for (int ks = 0; ks < 9; ks++) {
            constexpr int KO_T[9] = {0, 1, 2,
                                     0 + 1, 1 + 1, 2 + 1,
                                     0 + 2, 1 + 2, 2 + 2}; // placeholder (unused)
            const int KO = (ks / 3) * TIWP + (ks % 3);     // compile-time per ks
            (void)KO_T;
            uint32_t a0[M], a1[M], a2[M], a3[M];
            #pragma unroll
            for (int m = 0; m < M; m++) {
                const uint32_t* ap = ((M == 2 && m == 1) ? ap1 : ap0) + ks * 8;
                uint2 lo = *reinterpret_cast<const uint2*>(ap);            // a0,a2
                uint2 hi = *reinterpret_cast<const uint2*>(ap + 8 * WSTR); // a1,a3
                a0[m] = lo.x; a2[m] = lo.y;
                a1[m] = hi.x; a3[m] = hi.y;
            }
            #pragma unroll
            for (int t = 0; t < 4; t++) {
                uint32_t b0 = bp1[KO + t * 8 * STRIDE];
                uint32_t b1 = bp2[KO + t * 8 * STRIDE];
                #pragma unroll
                for (int m = 0; m < M; m++)
                    mma_f16(acc[m][t], a0[m], a1[m], a2[m], a3[m], b0, b1);
            }
        }
        __syncthreads();
    }

    // Epilogue: pair up (even, odd) co via shfl_xor(4), store half2 (u32x2).
    const int hrow = by * TH + nq;
    const size_t HWo = (size_t)Hout * Wout;
    #pragma unroll
    for (int m = 0; m < M; m++) {
        const int cb = (TH == 8) ? m * 16 : mh * 16;
        const int cbg = g * 32 + cb;
        #pragma unroll
        for (int t = 0; t < 4; t++) {
            float v0 = acc[m][t][0], v1 = acc[m][t][1];
            float v2 = acc[m][t][2], v3 = acc[m][t][3];
            if (BR) {
                v0 = fmaxf(v0, 0.0f); v1 = fmaxf(v1, 0.0f);
                v2 = fmaxf(v2, 0.0f); v3 = fmaxf(v3, 0.0f);
            }
            float p0 = __shfl_xor_sync(0xffffffffu, v0, 4);
            float p1 = __shfl_xor_sync(0xffffffffu, v1, 4);
            float p2 = __shfl_xor_sync(0xffffffffu, v2, 4);
            float p3 = __shfl_xor_sync(0xffffffffu, v3, 4);
            const int wg = bx * 32 + t * 8 + 2 * tig;
            uint2 st2;
            int copair;
            if ((gid & 1) == 0) {
                st2.x = packh2(v0, p0);
                st2.y = packh2(v1, p1);
                copair = (cbg + gid) >> 1;
            } else {
                st2.x = packh2(p2, v2);
                st2.y = packh2(p3, v3);
                copair = (cbg + gid + 7) >> 1;
            }
            *reinterpret_cast<uint2*>(
                out + ((size_t)b * (Cout / 2) + copair) * HWo
                    + (size_t)hrow * Wout + wg) = st2;
        }
    }
}

// ---------------------------------------------------------------------------
// ConvOffset2D bilinear sampling on interleaved-half2 buffers.
// Torch raw-reshape: offsets for output G are flat indices (2G, 2G+1) —
// adjacent u32 words in the interleaved layout (2G even) -> one uint2 load.
// ---------------------------------------------------------------------------
__global__ void deform_h(const uint32_t* __restrict__ x,
                         const uint32_t* __restrict__ off,
                         uint32_t* __restrict__ out,
                         int wsh, int hsh, int csh, int total_pairs)
{
    int idx = blockIdx.x * 256 + threadIdx.x;
    if (idx >= total_pairs) return;
    const int W = 1 << wsh, H = 1 << hsh;
    const int sh2 = wsh + hsh;
    const unsigned HW = 1u << sh2;
    const int C = 1 << csh;

    int p = idx & (HW - 1);
    int cpair = (idx >> sh2) & ((1 << (csh - 1)) - 1);
    int b = idx >> (sh2 + csh - 1);
    int h = p >> wsh, wcol = p & (W - 1);

    const uint32_t* xb = x + (size_t)b * (C / 2) * HW;
    const uint32_t* ob = off + (size_t)b * C * HW;   // off has 2C chans = C pairs

    float res[2];
    #pragma unroll
    for (int par = 0; par < 2; par++) {
        int c = 2 * cpair + par;
        unsigned G = (unsigned)c * HW + (unsigned)p;
        unsigned F0 = 2u * G;                      // even -> pp0 even
        unsigned co0 = F0 >> sh2, pp0 = F0 & (HW - 1);
        uint2 ow2 = *reinterpret_cast<const uint2*>(
            ob + (size_t)(co0 >> 1) * HW + pp0);   // 8B-aligned (pp0 even)
        float o0 = unpackh(ow2.x, co0 & 1);
        float o1 = unpackh(ow2.y, co0 & 1);

        float r  = fminf(fmaxf(o0 + (float)h,    0.0f), (float)(H - 1));
        float cc = fminf(fmaxf(o1 + (float)wcol, 0.0f), (float)(W - 1));
        float r0f = floorf(r), c0f = floorf(cc);
        int r0 = (int)r0f, r1 = (int)ceilf(r);
        int c0 = (int)c0f, c1 = (int)ceilf(cc);

        const uint32_t* xp = xb + (size_t)cpair * HW;
        float vlt = unpackh(xp[(r0 << wsh) + c0], par);
        float vrb = unpackh(xp[(r1 << wsh) + c1], par);
        float vlb = unpackh(xp[(r0 << wsh) + c1], par);
        float vrt = unpackh(xp[(r1 << wsh) + c0], par);
        float fr = r - r0f, fc = cc - c0f;
        float vt = vlt + (vrt - vlt) * fr;
        float vb = vlb + (vrb - vlb) * fr;
        res[par] = vt + (vb - vt) * fc;
    }
    out[idx] = packh2(res[0], res[1]);
}

// ---------------------------------------------------------------------------
// Weight prepass (ONE launch): all 7 tensors -> half2, layout
// [g][ch(16ci)][co32][ks(9)][e(8)] where e=2*tig+s -> cipair = s?tig+4:tig,
// half2 = (W[ci even], W[ci odd]) at tap ks.
// ---------------------------------------------------------------------------
struct PrepDesc {
    const float* src[7];
    int cin[7];
    int off[8];         // prefix sums in u32 elements
};

__global__ void prep_all_h(PrepDesc d, uint32_t* __restrict__ dst)
{
    int i = blockIdx.x * 256 + threadIdx.x;
    if (i >= d.off[7]) return;
    int s = 0;
    #pragma unroll
    for (int k = 0; k < 6; k++) s += (i >= d.off[k + 1]) ? 1 : 0;
    int j = i - d.off[s];
    const int CIN = d.cin[s];
    const int NCH = CIN >> 4;

    int e  = j & 7;
    int ks = (j >> 3) % 9;
    int rest = j / 72;
    int co = rest & 31; rest >>= 5;
    int ch = rest % NCH;
    int gi = rest / NCH;
    int cipair = (e & 1) ? (e >> 1) + 4 : (e >> 1);
    int ci = ch * 16 + cipair * 2;
    const float* sp = d.src[s] + (((size_t)(gi * 32 + co)) * CIN + ci) * 9 + ks;
    dst[i] = packh2(sp[0], sp[9]);
}

// ---------------------------------------------------------------------------
// x prepass: NCHW f32 -> interleaved half2 (vectorized 4 px/thread).
// ---------------------------------------------------------------------------
__global__ void cvt_x4(const float4* __restrict__ src, uint4* __restrict__ dst,
                       int sh2m2, int total4)
{
    int i = blockIdx.x * 256 + threadIdx.x;
    if (i >= total4) return;
    int poff = i & ((1 << sh2m2) - 1);
    int pair = i >> sh2m2;
    float4 a = src[(((size_t)pair * 2)     << sh2m2) + poff];
    float4 c = src[(((size_t)pair * 2 + 1) << sh2m2) + poff];
    dst[i] = make_uint4(packh2(a.x, c.x), packh2(a.y, c.y),
                        packh2(a.z, c.z), packh2(a.w, c.w));
}

// ---------------------------------------------------------------------------
// Global average pool from interleaved half2. One block per channel pair.
// ---------------------------------------------------------------------------
__global__ void avgpool_h(const uint32_t* __restrict__ in,
                          float* __restrict__ out, int HW, int halfC)
{
    const uint32_t* p = in + (size_t)blockIdx.x * HW;
    float lo = 0.0f, hi = 0.0f;
    for (int i = threadIdx.x; i < HW; i += 256) {
        float2 f = __half22float2(*reinterpret_cast<const __half2*>(p + i));
        lo += f.x; hi += f.y;
    }
    __shared__ float smlo[256], smhi[256];
    smlo[threadIdx.x] = lo; smhi[threadIdx.x] = hi;
    __syncthreads();
    for (int st = 128; st > 0; st >>= 1) {
        if (threadIdx.x < st) {
            smlo[threadIdx.x] += smlo[threadIdx.x + st];
            smhi[threadIdx.x] += smhi[threadIdx.x + st];
        }
        __syncthreads();
    }
    if (threadIdx.x == 0) {
        int b = blockIdx.x / halfC, cp = blockIdx.x % halfC;
        out[b * 2 * halfC + 2 * cp]     = smlo[0] / (float)HW;
        out[b * 2 * halfC + 2 * cp + 1] = smhi[0] / (float)HW;
    }
}

// ---------------------------------------------------------------------------
// Launch pipeline (graph-capturable: kernel launches + attribute sets only).
// ---------------------------------------------------------------------------
static inline int conv_smem_bytes(int stride, int th)
{
    int tih  = th * stride + 2;
    int tiwp = (32 * stride + 5 + 3) & ~3;
    int che  = tih * tiwp;
    int chep = ((che + 8 + 31) & ~31) | 8;
    int tile_n = 8 * chep;
    return (2 * tile_n + 2 * (32 * 72)) * 4;   // 45568 (s1) / 66048 (s2)
}

extern "C" void kernel_launch(void* const* d_in, const int* in_sizes, int n_in,
                              void* d_out, int out_size)
{
    const float* x   = (const float*)d_in[0];
    const float* w1  = (const float*)d_in[1];
    const float* b1  = (const float*)d_in[2];
    const float* ow1 = (const float*)d_in[3];
    const float* w2  = (const float*)d_in[4];
    const float* b2  = (const float*)d_in[5];
    const float* ow2 = (const float*)d_in[6];
    const float* w3  = (const float*)d_in[7];
    const float* b3  = (const float*)d_in[8];
    const float* ow3 = (const float*)d_in[9];
    const float* w4  = (const float*)d_in[10];
    const float* b4  = (const float*)d_in[11];
    float* outp = (float*)d_out;

    float *Af, *Bf, *Cf, *WTf;
    cudaGetSymbolAddress((void**)&Af, g_bufA);
    cudaGetSymbolAddress((void**)&Bf, g_bufB);
    cudaGetSymbolAddress((void**)&Cf, g_bufC);
    cudaGetSymbolAddress((void**)&WTf, g_wt);
    uint32_t* A  = (uint32_t*)Af;
    uint32_t* B  = (uint32_t*)Bf;
    uint32_t* C  = (uint32_t*)Cf;
    uint32_t* WT = (uint32_t*)WTf;

    const int S1 = conv_smem_bytes(1, 8), S2 = conv_smem_bytes(2, 4);
    cudaFuncSetAttribute(conv3x3_h<1, 32, 1, 8>, cudaFuncAttributeMaxDynamicSharedMemorySize, S1);
    cudaFuncSetAttribute(conv3x3_h<1, 32, 0, 8>, cudaFuncAttributeMaxDynamicSharedMemorySize, S1);
    cudaFuncSetAttribute(conv3x3_h<1, 64, 0, 8>, cudaFuncAttributeMaxDynamicSharedMemorySize, S1);
    cudaFuncSetAttribute(conv3x3_h<2, 32, 1, 4>, cudaFuncAttributeMaxDynamicSharedMemorySize, S2);
    cudaFuncSetAttribute(conv3x3_h<2, 64, 1, 4>, cudaFuncAttributeMaxDynamicSharedMemorySize, S2);

    // Prepacked weights (u32 offsets): w1 4608 | ow1 9216 | w2 9216 |
    // ow2 36864 | w3 9216 | ow3 9216 | w4 4608
    uint32_t* w1t  = WT;
    uint32_t* ow1t = WT + 4608;
    uint32_t* w2t  = WT + 13824;
    uint32_t* ow2t = WT + 23040;
    uint32_t* w3t  = WT + 59904;
    uint32_t* ow3t = WT + 69120;
    uint32_t* w4t  = WT + 78336;

    {
        PrepDesc d;
        d.src[0] = w1;  d.cin[0] = 32;
        d.src[1] = ow1; d.cin[1] = 32;
        d.src[2] = w2;  d.cin[2] = 32;
        d.src[3] = ow2; d.cin[3] = 64;
        d.src[4] = w3;  d.cin[4] = 64;
        d.src[5] = ow3; d.cin[5] = 32;
        d.src[6] = w4;  d.cin[6] = 32;
        d.off[0] = 0;     d.off[1] = 4608;  d.off[2] = 13824;
        d.off[3] = 23040; d.off[4] = 59904; d.off[5] = 69120;
        d.off[6] = 78336; d.off[7] = 82944;
        prep_all_h<<<(82944 + 255) / 256, 256>>>(d, WT);
    }
    {
        // x (16,32,256,256) f32 -> interleaved half2 in C
        int total4 = 16 * 16 * 65536 / 4;   // u32 count / 4
        cvt_x4<<<(total4 + 255) / 256, 256>>>((const float4*)x, (uint4*)C, 14, total4);
    }

    // 1) conv1: C(x~) -> A (16,32,256,256), bias+relu
    conv3x3_h<1, 32, 1, 8><<<dim3(8, 32, 16), 256, S1>>>(C, w1t, b1, A, 32, 256, 256);

    // 2) offconv1: A -> B (16,64,256,256)
    conv3x3_h<1, 32, 0, 8><<<dim3(8, 32, 32), 256, S1>>>(A, ow1t, nullptr, B, 64, 256, 256);

    // 3) deform1: A,B -> C (16,32,256,256) ; 16*16*65536 pairs
    deform_h<<<65536, 256>>>(A, B, C, 8, 8, 5, 16 * 16 * 65536);

    // 4) conv2 stride2: C -> A (16,64,128,128), bias+relu
    conv3x3_h<2, 32, 1, 4><<<dim3(4, 32, 32), 256, S2>>>(C, w2t, b2, A, 64, 256, 256);

    // 5) offconv2: A -> B (16,128,128,128)
    conv3x3_h<1, 64, 0, 8><<<dim3(4, 16, 64), 256, S1>>>(A, ow2t, nullptr, B, 128, 128, 128);

    // 6) deform2: A,B -> C (16,64,128,128) ; 16*32*16384 pairs
    deform_h<<<32768, 256>>>(A, B, C, 7, 7, 6, 16 * 32 * 16384);

    // 7) conv3 stride2: C -> A (16,32,64,64), bias+relu
    conv3x3_h<2, 64, 1, 4><<<dim3(2, 16, 16), 256, S2>>>(C, w3t, b3, A, 32, 128, 128);

    // 8) offconv3: A -> B (16,64,64,64)
    conv3x3_h<1, 32, 0, 8><<<dim3(2, 8, 32), 256, S1>>>(A, ow3t, nullptr, B, 64, 64, 64);

    // 9) deform3: A,B -> C (16,32,64,64) ; 16*16*4096 pairs
    deform_h<<<4096, 256>>>(A, B, C, 6, 6, 5, 16 * 16 * 4096);

    // 10) conv4 stride2: C -> A (16,32,32,32), bias+relu
    conv3x3_h<2, 32, 1, 4><<<dim3(1, 8, 16), 256, S2>>>(C, w4t, b4, A, 32, 64, 64);

    // 11) global avg pool: A (interleaved) -> out f32 (16,32,1,1)
    avgpool_h<<<256, 256>>>(A, outp, 1024, 16);
}

// round 10
// speedup vs baseline: 3.0631x; 1.0837x over previous
#include <cuda_runtime.h>
#include <cuda_fp16.h>
#include <cstdint>

// ---------------------------------------------------------------------------
// Scratch buffers (static __device__ globals — no allocation allowed).
// Activations live here as channel-pair-interleaved half2 (viewed as u32).
// ---------------------------------------------------------------------------
__device__ float g_bufA[33554432];
__device__ float g_bufB[67108864];
__device__ float g_bufC[33554432];
__device__ float g_wt[262144];          // prepacked half2 weights (u32 view)

// ---------------------------------------------------------------------------
// Helpers
// ---------------------------------------------------------------------------
__device__ __forceinline__ uint32_t packh2(float lo, float hi)
{
    __half2 h = __floats2half2_rn(lo, hi);   // .x = lo = low 16 bits
    return *reinterpret_cast<uint32_t*>(&h);
}

__device__ __forceinline__ float unpackh(uint32_t u, int parity)
{
    __half2 h = *reinterpret_cast<__half2*>(&u);
    return __half2float(parity ? __high2half(h) : __low2half(h));
}

__device__ __forceinline__ void mma_f16(float* c,
                                        uint32_t a0, uint32_t a1,
                                        uint32_t a2, uint32_t a3,
                                        uint32_t b0, uint32_t b1)
{
    asm volatile(
        "mma.sync.aligned.m16n8k16.row.col.f32.f16.f16.f32 "
        "{%0,%1,%2,%3}, {%4,%5,%6,%7}, {%8,%9}, {%0,%1,%2,%3};\n"
        : "+f"(c[0]), "+f"(c[1]), "+f"(c[2]), "+f"(c[3])
        : "r"(a0), "r"(a1), "r"(a2), "r"(a3), "r"(b0), "r"(b1));
}

__device__ __forceinline__ uint32_t smem_u32(const void* p)
{
    return (uint32_t)__cvta_generic_to_shared(p);
}

// 16B cp.async; src-size 0 -> 16 zero bytes written (halo padding).
__device__ __forceinline__ void cp16z(uint32_t dst, const void* src, bool ok)
{
    int sz = ok ? 16 : 0;
    asm volatile("cp.async.ca.shared.global [%0], [%1], 16, %2;"
                 :: "r"(dst), "l"(src), "r"(sz));
}

// ---------------------------------------------------------------------------
// Implicit-GEMM 3x3 conv (pad=1), fp16 mma.sync.m16n8k16, f32 accumulate,
// cp.async double-buffered pipeline. Activations channel-pair-interleaved
// half2 (one u32 per pixel per channel pair).
//
// K order: k = r*16 + cipair*2 + parity (r = dy*3+dx). Each k16 step = one
// kernel tap r; B fragments are single u32 LDS with compile-time offsets.
// Weight smem layout [cb2][ks][gid(8)][tig(4)][{a0,a1,a2,a3}]: the full A
// fragment is ONE LDS.128 at sw + cb2*1152 + ks*128 + lane*4 (lanes map to
// consecutive 16B -> conflict-free), and weight STAGING is a pure affine
// 16B copy (no div/mod).
// Tile staging descriptors (stride-1) hoisted into registers: computed once,
// source advances affinely by 8*HW per chunk.
// Output tile: 32 couts x (TH h x 32 w), 256 thr.
//   TH=8 (stride-1): warp = one row; M=2 co-tiles, B frags reused.
//   TH=4 (stride-2): warp = (co half, row); M=1.
// CHEP ≡ 8 (mod 32) -> stride-1 B loads conflict-free.
// ---------------------------------------------------------------------------
template<int STRIDE, int CIN, int BR, int TH>
__global__ __launch_bounds__(256, 3)
void conv3x3_h(const uint32_t* __restrict__ in, const uint32_t* __restrict__ w,
               const float* __restrict__ bias, uint32_t* __restrict__ out,
               int Cout, int Hin, int Win)
{
    constexpr int TW = 32;
    constexpr int M    = (TH == 8) ? 2 : 1;
    constexpr int TIH  = TH * STRIDE + 2;               // 10 / 10
    constexpr int TIWP = (TW * STRIDE + 5 + 3) & ~3;    // 40 / 72 (pixels=u32)
    constexpr int RU   = TIWP / 4;                      // 16B units per row
    constexpr int PL   = TIH * RU;                      // units per cp plane
    constexpr int CHE  = TIH * TIWP;
    constexpr int CHEP = ((CHE + 8 + 31) & ~31) | 8;    // ≡8 mod 32 (424/744)
    constexpr int TILE_N = 8 * CHEP;                    // u32 per tile buffer
    constexpr int NCH  = CIN / 16;                      // 16 ci per chunk
    constexpr int WN   = 2304;                          // u32 per weight chunk
    constexpr int TU   = 8 * PL;
    constexpr int TITER = (TU + 255) / 256;
    constexpr bool HOIST = (STRIDE == 1);

    extern __shared__ __align__(16) uint32_t smem[];    // [tile0|tile1|w0|w1]

    const int Hout = Hin / STRIDE, Wout = Win / STRIDE;
    const int tid = threadIdx.x;
    const int groups = Cout >> 5;
    const int g  = blockIdx.z % groups;
    const int b  = blockIdx.z / groups;
    const int bx = blockIdx.x, by = blockIdx.y;

    const int y0 = by * TH * STRIDE - 1;
    const int x0 = bx * TW * STRIDE - 4;    // 16B-aligned halo (logical -1 = col 3)
    const size_t HW = (size_t)Hin * Win;    // u32 per channel pair
    const uint32_t* ibase = in + (size_t)b * (CIN / 2) * HW;
    const uint32_t* wbase = w + (size_t)g * NCH * WN;

    const uint32_t tile_s = smem_u32(smem);
    const uint32_t wbuf_s = smem_u32(smem + 2 * TILE_N);

    // --- hoisted tile-staging descriptors (stride-1 only) ---
    int      h_soff[TITER];     // signed 32-bit gmem offset from ibase
    uint32_t h_doff[TITER];     // smem byte offset within tile buffer
    bool     h_ok[TITER];
    if (HOIST) {
        #pragma unroll
        for (int it = 0; it < TITER; it++) {
            int u = tid + it * 256;
            int uc = (u < TU) ? u : 0;
            int cp8 = uc / PL;
            int rem = uc - cp8 * PL;
            int r = rem / RU, uu = rem - r * RU;
            int gy = y0 + r, gx = x0 + 4 * uu;
            h_ok[it]   = (gy >= 0) && (gy < Hin) && (gx >= 0) && (gx < Win);
            h_soff[it] = cp8 * (int)HW + gy * Win + gx;
            h_doff[it] = 4u * (uint32_t)(cp8 * CHEP + r * TIWP + 4 * uu);
        }
    }

    auto load_chunk = [&](int ch, int bi) {
        const uint32_t* isrc = ibase + (size_t)(ch * 8) * HW;
        uint32_t td = tile_s + (bi ? 4u * TILE_N : 0u);
        if (HOIST) {
            #pragma unroll
            for (int it = 0; it < TITER; it++)
                if (tid + it * 256 < TU)
                    cp16z(td + h_doff[it], isrc + h_soff[it], h_ok[it]);
        } else {
            #pragma unroll 4
            for (int u = tid; u < TU; u += 256) {
                int cp8 = u / PL;
                int rem = u - cp8 * PL;
                int r = rem / RU, uu = rem - r * RU;
                int gy = y0 + r, gx = x0 + 4 * uu;
                bool ok = (gy >= 0) && (gy < Hin) && (gx >= 0) && (gx < Win);
                cp16z(td + 4u * (uint32_t)(cp8 * CHEP + r * TIWP + 4 * uu),
                      isrc + (size_t)cp8 * HW + (size_t)gy * Win + gx, ok);
            }
        }
        // Weights: pure affine 16B copy (layout is staging-order linear).
        const uint32_t* wsrc = wbase + ch * WN;
        uint32_t wd = wbuf_s + (bi ? 4u * WN : 0u);
        #pragma unroll 3
        for (int u = tid; u < WN / 4; u += 256)
            cp16z(wd + 16u * (uint32_t)u, wsrc + 4 * u, true);
        asm volatile("cp.async.commit_group;");
    };

    const int lane = tid & 31, wid = tid >> 5;
    const int tig = lane & 3, gid = lane >> 2;
    const int mh = (TH == 8) ? 0 : (wid & 1);
    const int nq = (TH == 8) ? wid : (wid >> 1);

    float acc[M][4][4];
    #pragma unroll
    for (int m = 0; m < M; m++) {
        const int cb = (TH == 8) ? m * 16 : mh * 16;
        float bv0 = 0.0f, bv1 = 0.0f;
        if (BR) {
            bv0 = bias[g * 32 + cb + gid];
            bv1 = bias[g * 32 + cb + gid + 8];
        }
        #pragma unroll
        for (int t = 0; t < 4; t++) {
            acc[m][t][0] = bv0; acc[m][t][1] = bv0;
            acc[m][t][2] = bv1; acc[m][t][3] = bv1;
        }
    }

    load_chunk(0, 0);

    #pragma unroll
    for (int ch = 0; ch < NCH; ch++) {
        const int cur = ch & 1;
        if (ch + 1 < NCH) {
            load_chunk(ch + 1, cur ^ 1);
            asm volatile("cp.async.wait_group 1;");
        } else {
            asm volatile("cp.async.wait_group 0;");
        }
        __syncthreads();

        const uint32_t* st = smem + cur * TILE_N;
        const uint32_t* sw = smem + 2 * TILE_N + cur * WN;
        // Register bases; all tap/pixel offsets are compile-time immediates.
        const uint32_t* bp1 = st + tig * CHEP + nq * STRIDE * TIWP + gid * STRIDE + 3;
        const uint32_t* bp2 = bp1 + 4 * CHEP;
        const uint32_t* apb = sw + ((TH == 8) ? 0 : mh * 1152) + 4 * lane;

        #pragma unroll
        for (int ks = 0; ks < 9; ks++) {
            const int KO = (ks / 3) * TIWP + (ks % 3);   // compile-time per ks
            uint4 va[M];
            #pragma unroll
            for (int m = 0; m < M; m++)
                va[m] = *reinterpret_cast<const uint4*>(apb + m * 1152 + ks * 128);
            #pragma unroll
            for (int t = 0; t < 4; t++) {
                uint32_t b0 = bp1[KO + t * 8 * STRIDE];
                uint32_t b1 = bp2[KO + t * 8 * STRIDE];
                #pragma unroll
                for (int m = 0; m < M; m++)
                    mma_f16(acc[m][t], va[m].x, va[m].y, va[m].z, va[m].w, b0, b1);
            }
        }
        __syncthreads();
    }

    // Epilogue: pair up (even, odd) co via shfl_xor(4), store half2 (u32x2).
    const int hrow = by * TH + nq;
    const size_t HWo = (size_t)Hout * Wout;
    #pragma unroll
    for (int m = 0; m < M; m++) {
        const int cb = (TH == 8) ? m * 16 : mh * 16;
        const int cbg = g * 32 + cb;
        #pragma unroll
        for (int t = 0; t < 4; t++) {
            float v0 = acc[m][t][0], v1 = acc[m][t][1];
            float v2 = acc[m][t][2], v3 = acc[m][t][3];
            if (BR) {
                v0 = fmaxf(v0, 0.0f); v1 = fmaxf(v1, 0.0f);
                v2 = fmaxf(v2, 0.0f); v3 = fmaxf(v3, 0.0f);
            }
            float p0 = __shfl_xor_sync(0xffffffffu, v0, 4);
            float p1 = __shfl_xor_sync(0xffffffffu, v1, 4);
            float p2 = __shfl_xor_sync(0xffffffffu, v2, 4);
            float p3 = __shfl_xor_sync(0xffffffffu, v3, 4);
            const int wg = bx * 32 + t * 8 + 2 * tig;
            uint2 st2;
            int copair;
            if ((gid & 1) == 0) {
                st2.x = packh2(v0, p0);
                st2.y = packh2(v1, p1);
                copair = (cbg + gid) >> 1;
            } else {
                st2.x = packh2(p2, v2);
                st2.y = packh2(p3, v3);
                copair = (cbg + gid + 7) >> 1;
            }
            *reinterpret_cast<uint2*>(
                out + ((size_t)b * (Cout / 2) + copair) * HWo
                    + (size_t)hrow * Wout + wg) = st2;
        }
    }
}

// ---------------------------------------------------------------------------
// ConvOffset2D bilinear sampling on interleaved-half2 buffers.
// Torch raw-reshape: offsets for output G are flat indices (2G, 2G+1) —
// adjacent u32 words in the interleaved layout (2G even) -> one uint2 load.
// ---------------------------------------------------------------------------
__global__ void deform_h(const uint32_t* __restrict__ x,
                         const uint32_t* __restrict__ off,
                         uint32_t* __restrict__ out,
                         int wsh, int hsh, int csh, int total_pairs)
{
    int idx = blockIdx.x * 256 + threadIdx.x;
    if (idx >= total_pairs) return;
    const int W = 1 << wsh, H = 1 << hsh;
    const int sh2 = wsh + hsh;
    const unsigned HW = 1u << sh2;
    const int C = 1 << csh;

    int p = idx & (HW - 1);
    int cpair = (idx >> sh2) & ((1 << (csh - 1)) - 1);
    int b = idx >> (sh2 + csh - 1);
    int h = p >> wsh, wcol = p & (W - 1);

    const uint32_t* xb = x + (size_t)b * (C / 2) * HW;
    const uint32_t* ob = off + (size_t)b * C * HW;   // off has 2C chans = C pairs

    float res[2];
    #pragma unroll
    for (int par = 0; par < 2; par++) {
        int c = 2 * cpair + par;
        unsigned G = (unsigned)c * HW + (unsigned)p;
        unsigned F0 = 2u * G;                      // even -> pp0 even
        unsigned co0 = F0 >> sh2, pp0 = F0 & (HW - 1);
        uint2 ow2 = *reinterpret_cast<const uint2*>(
            ob + (size_t)(co0 >> 1) * HW + pp0);   // 8B-aligned (pp0 even)
        float o0 = unpackh(ow2.x, co0 & 1);
        float o1 = unpackh(ow2.y, co0 & 1);

        float r  = fminf(fmaxf(o0 + (float)h,    0.0f), (float)(H - 1));
        float cc = fminf(fmaxf(o1 + (float)wcol, 0.0f), (float)(W - 1));
        float r0f = floorf(r), c0f = floorf(cc);
        int r0 = (int)r0f, r1 = (int)ceilf(r);
        int c0 = (int)c0f, c1 = (int)ceilf(cc);

        const uint32_t* xp = xb + (size_t)cpair * HW;
        float vlt = unpackh(xp[(r0 << wsh) + c0], par);
        float vrb = unpackh(xp[(r1 << wsh) + c1], par);
        float vlb = unpackh(xp[(r0 << wsh) + c1], par);
        float vrt = unpackh(xp[(r1 << wsh) + c0], par);
        float fr = r - r0f, fc = cc - c0f;
        float vt = vlt + (vrt - vlt) * fr;
        float vb = vlb + (vrb - vlb) * fr;
        res[par] = vt + (vb - vt) * fc;
    }
    out[idx] = packh2(res[0], res[1]);
}

// ---------------------------------------------------------------------------
// Weight prepass (ONE launch): all 7 tensors -> half2, NEW linear layout
// [g][ch(16ci)][cb2(2)][ks(9)][gid(8)][tig(4)][q(4)]:
//   q0/q1: co = g*32+cb2*16+gid / +8, k-pair cipair = tig
//   q2/q3: same cos, cipair = tig+4
// half2 = (W[ci even], W[ci odd]) at tap ks, ci = ch*16 + cipair*2.
// ---------------------------------------------------------------------------
struct PrepDesc {
    const float* src[7];
    int cin[7];
    int off[8];         // prefix sums in u32 elements
};

__global__ void prep_all_h(PrepDesc d, uint32_t* __restrict__ dst)
{
    int i = blockIdx.x * 256 + threadIdx.x;
    if (i >= d.off[7]) return;
    int s = 0;
    #pragma unroll
    for (int k = 0; k < 6; k++) s += (i >= d.off[k + 1]) ? 1 : 0;
    int j = i - d.off[s];
    const int CIN = d.cin[s];
    const int NCH = CIN >> 4;

    int q   = j & 3;
    int tig = (j >> 2) & 3;
    int gid = (j >> 4) & 7;
    int ks  = (j >> 7) % 9;
    int rest = j / 1152;
    int cb2 = rest & 1; rest >>= 1;
    int ch  = rest % NCH;
    int gi  = rest / NCH;

    int co = gi * 32 + cb2 * 16 + gid + (q & 1) * 8;
    int cipair = tig + (q >> 1) * 4;
    int ci = ch * 16 + cipair * 2;
    const float* sp = d.src[s] + (((size_t)co * CIN + ci) * 9 + ks);
    dst[i] = packh2(sp[0], sp[9]);
}

// ---------------------------------------------------------------------------
// x prepass: NCHW f32 -> interleaved half2 (vectorized 4 px/thread).
// ---------------------------------------------------------------------------
__global__ void cvt_x4(const float4* __restrict__ src, uint4* __restrict__ dst,
                       int sh2m2, int total4)
{
    int i = blockIdx.x * 256 + threadIdx.x;
    if (i >= total4) return;
    int poff = i & ((1 << sh2m2) - 1);
    int pair = i >> sh2m2;
    float4 a = src[(((size_t)pair * 2)     << sh2m2) + poff];
    float4 c = src[(((size_t)pair * 2 + 1) << sh2m2) + poff];
    dst[i] = make_uint4(packh2(a.x, c.x), packh2(a.y, c.y),
                        packh2(a.z, c.z), packh2(a.w, c.w));
}

// ---------------------------------------------------------------------------
// Global average pool from interleaved half2. One block per channel pair.
// ---------------------------------------------------------------------------
__global__ void avgpool_h(const uint32_t* __restrict__ in,
                          float* __restrict__ out, int HW, int halfC)
{
    const uint32_t* p = in + (size_t)blockIdx.x * HW;
    float lo = 0.0f, hi = 0.0f;
    for (int i = threadIdx.x; i < HW; i += 256) {
        float2 f = __half22float2(*reinterpret_cast<const __half2*>(p + i));
        lo += f.x; hi += f.y;
    }
    __shared__ float smlo[256], smhi[256];
    smlo[threadIdx.x] = lo; smhi[threadIdx.x] = hi;
    __syncthreads();
    for (int st = 128; st > 0; st >>= 1) {
        if (threadIdx.x < st) {
            smlo[threadIdx.x] += smlo[threadIdx.x + st];
            smhi[threadIdx.x] += smhi[threadIdx.x + st];
        }
        __syncthreads();
    }
    if (threadIdx.x == 0) {
        int b = blockIdx.x / halfC, cp = blockIdx.x % halfC;
        out[b * 2 * halfC + 2 * cp]     = smlo[0] / (float)HW;
        out[b * 2 * halfC + 2 * cp + 1] = smhi[0] / (float)HW;
    }
}

// ---------------------------------------------------------------------------
// Launch pipeline (graph-capturable: kernel launches + attribute sets only).
// ---------------------------------------------------------------------------
static inline int conv_smem_bytes(int stride, int th)
{
    int tih  = th * stride + 2;
    int tiwp = (32 * stride + 5 + 3) & ~3;
    int che  = tih * tiwp;
    int chep = ((che + 8 + 31) & ~31) | 8;
    int tile_n = 8 * chep;
    return (2 * tile_n + 2 * 2304) * 4;   // 45568 (s1) / 66048 (s2)
}

extern "C" void kernel_launch(void* const* d_in, const int* in_sizes, int n_in,
                              void* d_out, int out_size)
{
    const float* x   = (const float*)d_in[0];
    const float* w1  = (const float*)d_in[1];
    const float* b1  = (const float*)d_in[2];
    const float* ow1 = (const float*)d_in[3];
    const float* w2  = (const float*)d_in[4];
    const float* b2  = (const float*)d_in[5];
    const float* ow2 = (const float*)d_in[6];
    const float* w3  = (const float*)d_in[7];
    const float* b3  = (const float*)d_in[8];
    const float* ow3 = (const float*)d_in[9];
    const float* w4  = (const float*)d_in[10];
    const float* b4  = (const float*)d_in[11];
    float* outp = (float*)d_out;

    float *Af, *Bf, *Cf, *WTf;
    cudaGetSymbolAddress((void**)&Af, g_bufA);
    cudaGetSymbolAddress((void**)&Bf, g_bufB);
    cudaGetSymbolAddress((void**)&Cf, g_bufC);
    cudaGetSymbolAddress((void**)&WTf, g_wt);
    uint32_t* A  = (uint32_t*)Af;
    uint32_t* B  = (uint32_t*)Bf;
    uint32_t* C  = (uint32_t*)Cf;
    uint32_t* WT = (uint32_t*)WTf;

    const int S1 = conv_smem_bytes(1, 8), S2 = conv_smem_bytes(2, 4);
    cudaFuncSetAttribute(conv3x3_h<1, 32, 1, 8>, cudaFuncAttributeMaxDynamicSharedMemorySize, S1);
    cudaFuncSetAttribute(conv3x3_h<1, 32, 0, 8>, cudaFuncAttributeMaxDynamicSharedMemorySize, S1);
    cudaFuncSetAttribute(conv3x3_h<1, 64, 0, 8>, cudaFuncAttributeMaxDynamicSharedMemorySize, S1);
    cudaFuncSetAttribute(conv3x3_h<2, 32, 1, 4>, cudaFuncAttributeMaxDynamicSharedMemorySize, S2);
    cudaFuncSetAttribute(conv3x3_h<2, 64, 1, 4>, cudaFuncAttributeMaxDynamicSharedMemorySize, S2);

    // Prepacked weights (u32 offsets): w1 4608 | ow1 9216 | w2 9216 |
    // ow2 36864 | w3 9216 | ow3 9216 | w4 4608
    uint32_t* w1t  = WT;
    uint32_t* ow1t = WT + 4608;
    uint32_t* w2t  = WT + 13824;
    uint32_t* ow2t = WT + 23040;
    uint32_t* w3t  = WT + 59904;
    uint32_t* ow3t = WT + 69120;
    uint32_t* w4t  = WT + 78336;

    {
        PrepDesc d;
        d.src[0] = w1;  d.cin[0] = 32;
        d.src[1] = ow1; d.cin[1] = 32;
        d.src[2] = w2;  d.cin[2] = 32;
        d.src[3] = ow2; d.cin[3] = 64;
        d.src[4] = w3;  d.cin[4] = 64;
        d.src[5] = ow3; d.cin[5] = 32;
        d.src[6] = w4;  d.cin[6] = 32;
        d.off[0] = 0;     d.off[1] = 4608;  d.off[2] = 13824;
        d.off[3] = 23040; d.off[4] = 59904; d.off[5] = 69120;
        d.off[6] = 78336; d.off[7] = 82944;
        prep_all_h<<<(82944 + 255) / 256, 256>>>(d, WT);
    }
    {
        // x (16,32,256,256) f32 -> interleaved half2 in C
        int total4 = 16 * 16 * 65536 / 4;   // u32 count / 4
        cvt_x4<<<(total4 + 255) / 256, 256>>>((const float4*)x, (uint4*)C, 14, total4);
    }

    // 1) conv1: C(x~) -> A (16,32,256,256), bias+relu
    conv3x3_h<1, 32, 1, 8><<<dim3(8, 32, 16), 256, S1>>>(C, w1t, b1, A, 32, 256, 256);

    // 2) offconv1: A -> B (16,64,256,256)
    conv3x3_h<1, 32, 0, 8><<<dim3(8, 32, 32), 256, S1>>>(A, ow1t, nullptr, B, 64, 256, 256);

    // 3) deform1: A,B -> C (16,32,256,256) ; 16*16*65536 pairs
    deform_h<<<65536, 256>>>(A, B, C, 8, 8, 5, 16 * 16 * 65536);

    // 4) conv2 stride2: C -> A (16,64,128,128), bias+relu
    conv3x3_h<2, 32, 1, 4><<<dim3(4, 32, 32), 256, S2>>>(C, w2t, b2, A, 64, 256, 256);

    // 5) offconv2: A -> B (16,128,128,128)
    conv3x3_h<1, 64, 0, 8><<<dim3(4, 16, 64), 256, S1>>>(A, ow2t, nullptr, B, 128, 128, 128);

    // 6) deform2: A,B -> C (16,64,128,128) ; 16*32*16384 pairs
    deform_h<<<32768, 256>>>(A, B, C, 7, 7, 6, 16 * 32 * 16384);

    // 7) conv3 stride2: C -> A (16,32,64,64), bias+relu
    conv3x3_h<2, 64, 1, 4><<<dim3(2, 16, 16), 256, S2>>>(C, w3t, b3, A, 32, 128, 128);

    // 8) offconv3: A -> B (16,64,64,64)
    conv3x3_h<1, 32, 0, 8><<<dim3(2, 8, 32), 256, S1>>>(A, ow3t, nullptr, B, 64, 64, 64);

    // 9) deform3: A,B -> C (16,32,64,64) ; 16*16*4096 pairs
    deform_h<<<4096, 256>>>(A, B, C, 6, 6, 5, 16 * 16 * 4096);

    // 10) conv4 stride2: C -> A (16,32,32,32), bias+relu
    conv3x3_h<2, 32, 1, 4><<<dim3(1, 8, 16), 256, S2>>>(C, w4t, b4, A, 32, 64, 64);

    // 11) global avg pool: A (interleaved) -> out f32 (16,32,1,1)
    avgpool_h<<<256, 256>>>(A, outp, 1024, 16);
}